// round 1
// baseline (speedup 1.0000x reference)
#include <cuda_runtime.h>
#include <cuda_bf16.h>
#include <math.h>

// ---------------- problem constants ----------------
#define SEQ      2048
#define HIDDEN   2048
#define N_HEADS  32
#define N_KV     8
#define HEAD_DIM 64
#define KV_DIM   (N_KV * HEAD_DIM)   // 512

// ---------------- scratch (static device globals; no allocs allowed) -------
__device__ float g_q[SEQ * HIDDEN];   // [s, 32, 64]
__device__ float g_k[SEQ * KV_DIM];   // [s, 8, 64]
__device__ float g_v[SEQ * KV_DIM];   // [s, 8, 64]
__device__ float g_o[SEQ * HIDDEN];   // attention output [s, 32*64]

// ---------------- SGEMM: C[M,N] = A[M,K] @ B[K,N] + bias[N] ----------------
// 128x128 block tile, 8x8 thread tile, BK=8, 256 threads.
// Requires M%128==0, N%128==0, K%8==0 (true for all our shapes).
#define BM 128
#define BN 128
#define BK 8
#define TM 8
#define TN 8

__global__ __launch_bounds__(256) void sgemm_bias_kernel(
    const float* __restrict__ A, const float* __restrict__ B,
    const float* __restrict__ bias, float* __restrict__ C,
    int M, int N, int K)
{
    __shared__ float As[BK][BM];   // transposed A tile
    __shared__ float Bs[BK][BN];

    const int bx = blockIdx.x;     // N tile
    const int by = blockIdx.y;     // M tile
    const int tid = threadIdx.x;

    const int tx = tid % 16;       // 16 thread-cols * TN(8) = 128
    const int ty = tid / 16;       // 16 thread-rows * TM(8) = 128

    // A tile load mapping: 128 rows x 8 cols = 1024 floats = 256 float4
    const int a_row = tid / 2;           // 0..127
    const int a_col = (tid % 2) * 4;     // 0 or 4
    // B tile load mapping: 8 rows x 128 cols = 1024 floats = 256 float4
    const int b_row = tid / 32;          // 0..7
    const int b_col = (tid % 32) * 4;    // 0..124

    const float* Aptr = A + (size_t)(by * BM + a_row) * K + a_col;
    const float* Bptr = B + (size_t)b_row * N + bx * BN + b_col;

    float acc[TM][TN];
#pragma unroll
    for (int i = 0; i < TM; i++)
#pragma unroll
        for (int j = 0; j < TN; j++) acc[i][j] = 0.f;

    for (int k0 = 0; k0 < K; k0 += BK) {
        float4 a4 = *(const float4*)(Aptr + k0);
        As[a_col + 0][a_row] = a4.x;
        As[a_col + 1][a_row] = a4.y;
        As[a_col + 2][a_row] = a4.z;
        As[a_col + 3][a_row] = a4.w;
        float4 b4 = *(const float4*)(Bptr + (size_t)k0 * N);
        *(float4*)&Bs[b_row][b_col] = b4;
        __syncthreads();

#pragma unroll
        for (int kk = 0; kk < BK; kk++) {
            float ar[TM], br[TN];
#pragma unroll
            for (int i = 0; i < TM; i++) ar[i] = As[kk][ty * TM + i];
#pragma unroll
            for (int j = 0; j < TN; j++) br[j] = Bs[kk][tx * TN + j];
#pragma unroll
            for (int i = 0; i < TM; i++)
#pragma unroll
                for (int j = 0; j < TN; j++)
                    acc[i][j] = fmaf(ar[i], br[j], acc[i][j]);
        }
        __syncthreads();
    }

#pragma unroll
    for (int i = 0; i < TM; i++) {
        int row = by * BM + ty * TM + i;
#pragma unroll
        for (int j = 0; j < TN; j++) {
            int col = bx * BN + tx * TN + j;
            C[(size_t)row * N + col] = acc[i][j] + bias[col];
        }
    }
}

// ---------------- fused per-head LayerNorm + RoPE ---------------------------
// buf layout: [seq, heads, 64]. One warp per row; lane handles (d, d+32).
__global__ void ln_rope_kernel(float* __restrict__ buf,
                               const float* __restrict__ gamma,
                               const float* __restrict__ beta,
                               int heads, int seq)
{
    int row = blockIdx.x * blockDim.y + threadIdx.y;
    int total = seq * heads;
    if (row >= total) return;
    int s = row / heads;
    int lane = threadIdx.x;

    float* p = buf + (size_t)row * HEAD_DIM;
    float x0 = p[lane];
    float x1 = p[lane + 32];

    float sum = x0 + x1;
    float sq  = x0 * x0 + x1 * x1;
#pragma unroll
    for (int o = 16; o > 0; o >>= 1) {
        sum += __shfl_xor_sync(0xFFFFFFFFu, sum, o);
        sq  += __shfl_xor_sync(0xFFFFFFFFu, sq,  o);
    }
    float mean = sum * (1.0f / 64.0f);
    float var  = sq * (1.0f / 64.0f) - mean * mean;
    float inv  = rsqrtf(var + 1e-5f);

    float y0 = (x0 - mean) * inv * gamma[lane]      + beta[lane];
    float y1 = (x1 - mean) * inv * gamma[lane + 32] + beta[lane + 32];

    // RoPE: inv_freq = theta^{-lane/32}; out[d]=y0*c - y1*s; out[d+32]=y1*c + y0*s
    double freq = pow(10000.0, -(double)lane / 32.0);
    double ang  = (double)s * freq;
    float c = (float)cos(ang);
    float sn = (float)sin(ang);

    p[lane]      = y0 * c - y1 * sn;
    p[lane + 32] = y1 * c + y0 * sn;
}

// ---------------- flash attention (fp32, non-causal, GQA) -------------------
// grid: (SEQ/BQ, N_HEADS). 256 threads. Each thread owns (q_row, 16 out dims).
#define BQ 64
#define BKT 32

__global__ __launch_bounds__(256) void attn_kernel(
    const float* __restrict__ q, const float* __restrict__ k,
    const float* __restrict__ v, float* __restrict__ out)
{
    __shared__ float Qs[BQ][HEAD_DIM + 1];
    __shared__ float Ks[BKT][HEAD_DIM + 1];
    __shared__ float Vs[BKT][HEAD_DIM + 1];
    __shared__ float Ss[BQ][BKT + 1];

    const int h  = blockIdx.y;         // q head
    const int g  = h >> 2;             // kv head
    const int q0 = blockIdx.x * BQ;
    const int tid = threadIdx.x;
    const int row = tid >> 2;          // 0..63
    const int cseg = tid & 3;          // 4 x 16-dim output segments
    const int cs = cseg * 16;
    const int j0 = cseg * 8;           // 8 score cols per thread

    // load Q tile [64][64] (coalesced scalar)
    for (int i = tid; i < BQ * HEAD_DIM; i += 256) {
        int r = i >> 6, c = i & 63;
        Qs[r][c] = q[(size_t)(q0 + r) * HIDDEN + h * HEAD_DIM + c];
    }

    float m = -1e30f, l = 0.f;
    float acc[16];
#pragma unroll
    for (int d = 0; d < 16; d++) acc[d] = 0.f;

    for (int k0 = 0; k0 < SEQ; k0 += BKT) {
        // load K,V tiles [32][64]
        for (int i = tid; i < BKT * HEAD_DIM; i += 256) {
            int r = i >> 6, c = i & 63;
            Ks[r][c] = k[(size_t)(k0 + r) * KV_DIM + g * HEAD_DIM + c];
            Vs[r][c] = v[(size_t)(k0 + r) * KV_DIM + g * HEAD_DIM + c];
        }
        __syncthreads();

        // scores: this thread computes S[row][j0..j0+8)
        float sc[8];
#pragma unroll
        for (int jj = 0; jj < 8; jj++) sc[jj] = 0.f;
#pragma unroll 16
        for (int d = 0; d < HEAD_DIM; d++) {
            float qd = Qs[row][d];
#pragma unroll
            for (int jj = 0; jj < 8; jj++)
                sc[jj] = fmaf(qd, Ks[j0 + jj][d], sc[jj]);
        }
#pragma unroll
        for (int jj = 0; jj < 8; jj++) Ss[row][j0 + jj] = sc[jj] * 0.125f;
        __syncwarp();  // the 4 threads of a row are in the same warp

        // online softmax over this tile (each of the 4 row-threads redundantly)
        float mt = m;
#pragma unroll 8
        for (int j = 0; j < BKT; j++) mt = fmaxf(mt, Ss[row][j]);
        float alpha = __expf(m - mt);
        m = mt;
        l *= alpha;
#pragma unroll
        for (int d = 0; d < 16; d++) acc[d] *= alpha;
#pragma unroll 4
        for (int j = 0; j < BKT; j++) {
            float p = __expf(Ss[row][j] - mt);
            l += p;
#pragma unroll
            for (int d = 0; d < 16; d++)
                acc[d] = fmaf(p, Vs[j][cs + d], acc[d]);
        }
        __syncthreads();  // protect Ks/Vs before next tile load
    }

    float invl = 1.0f / l;
#pragma unroll
    for (int d = 0; d < 16; d++)
        out[(size_t)(q0 + row) * HIDDEN + h * HEAD_DIM + cs + d] = acc[d] * invl;
}

// ---------------- launch --------------------------------------------------
extern "C" void kernel_launch(void* const* d_in, const int* in_sizes, int n_in,
                              void* d_out, int out_size)
{
    const float* x   = (const float*)d_in[0];
    const float* Wq  = (const float*)d_in[1];
    const float* bq  = (const float*)d_in[2];
    const float* Wk  = (const float*)d_in[3];
    const float* bk  = (const float*)d_in[4];
    const float* Wv  = (const float*)d_in[5];
    const float* bv  = (const float*)d_in[6];
    const float* Wo  = (const float*)d_in[7];
    const float* bo  = (const float*)d_in[8];
    const float* q_g = (const float*)d_in[9];
    const float* q_b = (const float*)d_in[10];
    const float* k_g = (const float*)d_in[11];
    const float* k_b = (const float*)d_in[12];
    float* out = (float*)d_out;

    void *pq, *pk, *pv, *po;
    cudaGetSymbolAddress(&pq, g_q);
    cudaGetSymbolAddress(&pk, g_k);
    cudaGetSymbolAddress(&pv, g_v);
    cudaGetSymbolAddress(&po, g_o);
    float* fq = (float*)pq;
    float* fk = (float*)pk;
    float* fv = (float*)pv;
    float* fo = (float*)po;

    // Q/K/V projections
    {
        dim3 grid(HIDDEN / BN, SEQ / BM);
        sgemm_bias_kernel<<<grid, 256>>>(x, Wq, bq, fq, SEQ, HIDDEN, HIDDEN);
    }
    {
        dim3 grid(KV_DIM / BN, SEQ / BM);
        sgemm_bias_kernel<<<grid, 256>>>(x, Wk, bk, fk, SEQ, KV_DIM, HIDDEN);
        sgemm_bias_kernel<<<grid, 256>>>(x, Wv, bv, fv, SEQ, KV_DIM, HIDDEN);
    }

    // per-head LN + RoPE (q: 32 heads, k: 8 heads)
    {
        dim3 blk(32, 4);
        int rows_q = SEQ * N_HEADS;
        int rows_k = SEQ * N_KV;
        ln_rope_kernel<<<(rows_q + 3) / 4, blk>>>(fq, q_g, q_b, N_HEADS, SEQ);
        ln_rope_kernel<<<(rows_k + 3) / 4, blk>>>(fk, k_g, k_b, N_KV, SEQ);
    }

    // attention
    {
        dim3 grid(SEQ / BQ, N_HEADS);
        attn_kernel<<<grid, 256>>>(fq, fk, fv, fo);
    }

    // output projection
    {
        dim3 grid(HIDDEN / BN, SEQ / BM);
        sgemm_bias_kernel<<<grid, 256>>>(fo, Wo, bo, out, SEQ, HIDDEN, HIDDEN);
    }
}

// round 2
// speedup vs baseline: 1.1867x; 1.1867x over previous
#include <cuda_runtime.h>
#include <cuda_bf16.h>
#include <math.h>

// ---------------- problem constants ----------------
#define SEQ      2048
#define HIDDEN   2048
#define N_HEADS  32
#define N_KV     8
#define HEAD_DIM 64
#define KV_DIM   (N_KV * HEAD_DIM)   // 512

// ---------------- scratch (static device globals; no allocs allowed) -------
__device__ float g_q[SEQ * HIDDEN];   // [s, 32, 64]
__device__ float g_k[SEQ * KV_DIM];   // [s, 8, 64]
__device__ float g_v[SEQ * KV_DIM];   // [s, 8, 64]
__device__ float g_o[SEQ * HIDDEN];   // attention output [s, 32*64]

// ---------------- SGEMM: C[M,N] = A[M,K] @ B[K,N] + bias[N] ----------------
// 128x128 block tile, 8x8 thread tile, BK=8, 256 threads, double-buffered smem.
#define BM 128
#define BN 128
#define BK 8
#define TM 8
#define TN 8

__global__ __launch_bounds__(256) void sgemm_bias_kernel(
    const float* __restrict__ A, const float* __restrict__ B,
    const float* __restrict__ bias, float* __restrict__ C,
    int M, int N, int K)
{
    __shared__ float As[2][BK][BM];   // transposed A tile
    __shared__ float Bs[2][BK][BN];

    const int bx = blockIdx.x;     // N tile
    const int by = blockIdx.y;     // M tile
    const int tid = threadIdx.x;

    const int tx = tid % 16;       // 16 thread-cols * TN(8) = 128
    const int ty = tid / 16;       // 16 thread-rows * TM(8) = 128

    const int a_row = tid / 2;           // 0..127
    const int a_col = (tid % 2) * 4;     // 0 or 4
    const int b_row = tid / 32;          // 0..7
    const int b_col = (tid % 32) * 4;    // 0..124

    const float* Aptr = A + (size_t)(by * BM + a_row) * K + a_col;
    const float* Bptr = B + (size_t)b_row * N + bx * BN + b_col;

    float acc[TM][TN];
#pragma unroll
    for (int i = 0; i < TM; i++)
#pragma unroll
        for (int j = 0; j < TN; j++) acc[i][j] = 0.f;

    // prologue: tile 0 -> buffer 0
    {
        float4 a4 = *(const float4*)(Aptr);
        As[0][a_col + 0][a_row] = a4.x;
        As[0][a_col + 1][a_row] = a4.y;
        As[0][a_col + 2][a_row] = a4.z;
        As[0][a_col + 3][a_row] = a4.w;
        float4 b4 = *(const float4*)(Bptr);
        *(float4*)&Bs[0][b_row][b_col] = b4;
    }
    __syncthreads();

    int buf = 0;
    for (int k0 = 0; k0 < K; k0 += BK) {
        const int kn = k0 + BK;
        float4 a4n, b4n;
        const bool more = (kn < K);
        if (more) {
            a4n = *(const float4*)(Aptr + kn);
            b4n = *(const float4*)(Bptr + (size_t)kn * N);
        }

#pragma unroll
        for (int kk = 0; kk < BK; kk++) {
            float ar[TM], br[TN];
#pragma unroll
            for (int i = 0; i < TM; i++) ar[i] = As[buf][kk][ty * TM + i];
#pragma unroll
            for (int j = 0; j < TN; j++) br[j] = Bs[buf][kk][tx * TN + j];
#pragma unroll
            for (int i = 0; i < TM; i++)
#pragma unroll
                for (int j = 0; j < TN; j++)
                    acc[i][j] = fmaf(ar[i], br[j], acc[i][j]);
        }

        if (more) {
            const int nb = buf ^ 1;
            As[nb][a_col + 0][a_row] = a4n.x;
            As[nb][a_col + 1][a_row] = a4n.y;
            As[nb][a_col + 2][a_row] = a4n.z;
            As[nb][a_col + 3][a_row] = a4n.w;
            *(float4*)&Bs[nb][b_row][b_col] = b4n;
            __syncthreads();
            buf = nb;
        }
    }

#pragma unroll
    for (int i = 0; i < TM; i++) {
        int row = by * BM + ty * TM + i;
#pragma unroll
        for (int j = 0; j < TN; j++) {
            int col = bx * BN + tx * TN + j;
            C[(size_t)row * N + col] = acc[i][j] + bias[col];
        }
    }
}

// ---------------- fused per-head LayerNorm + RoPE ---------------------------
// buf layout: [seq, heads, 64]. One warp per row; lane handles (d, d+32).
// All angle math in fp32, mirroring the reference (which builds fp32 tables).
__global__ void ln_rope_kernel(float* __restrict__ buf,
                               const float* __restrict__ gamma,
                               const float* __restrict__ beta,
                               int heads, int seq)
{
    int row = blockIdx.x * blockDim.y + threadIdx.y;
    int total = seq * heads;
    if (row >= total) return;
    int s = row / heads;
    int lane = threadIdx.x;

    float* p = buf + (size_t)row * HEAD_DIM;
    float x0 = p[lane];
    float x1 = p[lane + 32];

    float sum = x0 + x1;
    float sq  = x0 * x0 + x1 * x1;
#pragma unroll
    for (int o = 16; o > 0; o >>= 1) {
        sum += __shfl_xor_sync(0xFFFFFFFFu, sum, o);
        sq  += __shfl_xor_sync(0xFFFFFFFFu, sq,  o);
    }
    float mean = sum * (1.0f / 64.0f);
    float var  = sq * (1.0f / 64.0f) - mean * mean;
    float inv  = rsqrtf(var + 1e-5f);

    float y0 = (x0 - mean) * inv * gamma[lane]      + beta[lane];
    float y1 = (x1 - mean) * inv * gamma[lane + 32] + beta[lane + 32];

    // RoPE (fp32, matching reference): inv_freq = 10000^(-lane/32)
    float freq = powf(10000.0f, -(float)lane * (1.0f / 32.0f));
    float ang  = (float)s * freq;
    float c, sn;
    sincosf(ang, &sn, &c);

    p[lane]      = y0 * c - y1 * sn;
    p[lane + 32] = y1 * c + y0 * sn;
}

// ---------------- flash attention (fp32, non-causal, GQA) -------------------
// grid: (SEQ/BQ, N_HEADS). 256 threads. Each thread owns (q_row, 16 out dims,
// 8 score cols). Softmax stats reduced across the 4-thread quad via shuffles.
#define BQ 64
#define BKT 32

__global__ __launch_bounds__(256) void attn_kernel(
    const float* __restrict__ q, const float* __restrict__ k,
    const float* __restrict__ v, float* __restrict__ out)
{
    __shared__ float Qs[BQ][HEAD_DIM + 1];
    __shared__ float Ks[BKT][HEAD_DIM + 1];
    __shared__ float Vs[BKT][HEAD_DIM + 1];
    __shared__ float Ps[BQ][BKT + 1];

    const int h  = blockIdx.y;         // q head
    const int g  = h >> 2;             // kv head
    const int q0 = blockIdx.x * BQ;
    const int tid = threadIdx.x;
    const int row = tid >> 2;          // 0..63
    const int cseg = tid & 3;          // 4 x 16-dim output segments
    const int cs = cseg * 16;
    const int j0 = cseg * 8;           // 8 score cols per thread

    // load Q tile [64][64]
    for (int i = tid; i < BQ * HEAD_DIM; i += 256) {
        int r = i >> 6, c = i & 63;
        Qs[r][c] = q[(size_t)(q0 + r) * HIDDEN + h * HEAD_DIM + c];
    }

    float m = -1e30f, l = 0.f;
    float acc[16];
#pragma unroll
    for (int d = 0; d < 16; d++) acc[d] = 0.f;

    for (int k0 = 0; k0 < SEQ; k0 += BKT) {
        // load K,V tiles [32][64]
        for (int i = tid; i < BKT * HEAD_DIM; i += 256) {
            int r = i >> 6, c = i & 63;
            Ks[r][c] = k[(size_t)(k0 + r) * KV_DIM + g * HEAD_DIM + c];
            Vs[r][c] = v[(size_t)(k0 + r) * KV_DIM + g * HEAD_DIM + c];
        }
        __syncthreads();

        // scores: this thread computes S[row][j0..j0+8)
        float sc[8];
#pragma unroll
        for (int jj = 0; jj < 8; jj++) sc[jj] = 0.f;
#pragma unroll 16
        for (int d = 0; d < HEAD_DIM; d++) {
            float qd = Qs[row][d];
#pragma unroll
            for (int jj = 0; jj < 8; jj++)
                sc[jj] = fmaf(qd, Ks[j0 + jj][d], sc[jj]);
        }
#pragma unroll
        for (int jj = 0; jj < 8; jj++) sc[jj] *= 0.125f;

        // quad-reduced online softmax
        float mp = sc[0];
#pragma unroll
        for (int jj = 1; jj < 8; jj++) mp = fmaxf(mp, sc[jj]);
        mp = fmaxf(mp, __shfl_xor_sync(0xFFFFFFFFu, mp, 1));
        mp = fmaxf(mp, __shfl_xor_sync(0xFFFFFFFFu, mp, 2));
        float mt = fmaxf(m, mp);
        float alpha = __expf(m - mt);
        m = mt;

        float lp = 0.f;
#pragma unroll
        for (int jj = 0; jj < 8; jj++) {
            float pv = __expf(sc[jj] - mt);
            lp += pv;
            Ps[row][j0 + jj] = pv;
        }
        lp += __shfl_xor_sync(0xFFFFFFFFu, lp, 1);
        lp += __shfl_xor_sync(0xFFFFFFFFu, lp, 2);
        l = l * alpha + lp;

#pragma unroll
        for (int d = 0; d < 16; d++) acc[d] *= alpha;
        __syncwarp();

#pragma unroll 4
        for (int j = 0; j < BKT; j++) {
            float pv = Ps[row][j];
#pragma unroll
            for (int d = 0; d < 16; d++)
                acc[d] = fmaf(pv, Vs[j][cs + d], acc[d]);
        }
        __syncthreads();  // protect Ks/Vs before next tile load
    }

    float invl = 1.0f / l;
#pragma unroll
    for (int d = 0; d < 16; d++)
        out[(size_t)(q0 + row) * HIDDEN + h * HEAD_DIM + cs + d] = acc[d] * invl;
}

// ---------------- launch --------------------------------------------------
extern "C" void kernel_launch(void* const* d_in, const int* in_sizes, int n_in,
                              void* d_out, int out_size)
{
    const float* x   = (const float*)d_in[0];
    const float* Wq  = (const float*)d_in[1];
    const float* bq  = (const float*)d_in[2];
    const float* Wk  = (const float*)d_in[3];
    const float* bk  = (const float*)d_in[4];
    const float* Wv  = (const float*)d_in[5];
    const float* bv  = (const float*)d_in[6];
    const float* Wo  = (const float*)d_in[7];
    const float* bo  = (const float*)d_in[8];
    const float* q_g = (const float*)d_in[9];
    const float* q_b = (const float*)d_in[10];
    const float* k_g = (const float*)d_in[11];
    const float* k_b = (const float*)d_in[12];
    float* out = (float*)d_out;

    void *pq, *pk, *pv, *po;
    cudaGetSymbolAddress(&pq, g_q);
    cudaGetSymbolAddress(&pk, g_k);
    cudaGetSymbolAddress(&pv, g_v);
    cudaGetSymbolAddress(&po, g_o);
    float* fq = (float*)pq;
    float* fk = (float*)pk;
    float* fv = (float*)pv;
    float* fo = (float*)po;

    // Q/K/V projections
    {
        dim3 grid(HIDDEN / BN, SEQ / BM);
        sgemm_bias_kernel<<<grid, 256>>>(x, Wq, bq, fq, SEQ, HIDDEN, HIDDEN);
    }
    {
        dim3 grid(KV_DIM / BN, SEQ / BM);
        sgemm_bias_kernel<<<grid, 256>>>(x, Wk, bk, fk, SEQ, KV_DIM, HIDDEN);
        sgemm_bias_kernel<<<grid, 256>>>(x, Wv, bv, fv, SEQ, KV_DIM, HIDDEN);
    }

    // per-head LN + RoPE (q: 32 heads, k: 8 heads)
    {
        dim3 blk(32, 4);
        int rows_q = SEQ * N_HEADS;
        int rows_k = SEQ * N_KV;
        ln_rope_kernel<<<(rows_q + 3) / 4, blk>>>(fq, q_g, q_b, N_HEADS, SEQ);
        ln_rope_kernel<<<(rows_k + 3) / 4, blk>>>(fk, k_g, k_b, N_KV, SEQ);
    }

    // attention
    {
        dim3 grid(SEQ / BQ, N_HEADS);
        attn_kernel<<<grid, 256>>>(fq, fk, fv, fo);
    }

    // output projection
    {
        dim3 grid(HIDDEN / BN, SEQ / BM);
        sgemm_bias_kernel<<<grid, 256>>>(fo, Wo, bo, out, SEQ, HIDDEN, HIDDEN);
    }
}

// round 3
// speedup vs baseline: 1.1905x; 1.0031x over previous
#include <cuda_runtime.h>
#include <cuda_bf16.h>
#include <math.h>
#include <stdint.h>

// ---------------- problem constants ----------------
#define SEQ      2048
#define HIDDEN   2048
#define N_HEADS  32
#define N_KV     8
#define HEAD_DIM 64
#define KV_DIM   (N_KV * HEAD_DIM)   // 512

// ---------------- scratch (static device globals; no allocs allowed) -------
__device__ float g_q[SEQ * HIDDEN];   // [s, 32, 64]
__device__ float g_k[SEQ * KV_DIM];   // [s, 8, 64]
__device__ float g_v[SEQ * KV_DIM];   // [s, 8, 64]
__device__ float g_o[SEQ * HIDDEN];   // attention output [s, 32*64]

// ============================================================================
// TF32 tensor-core GEMM: C[M,N] = A[M,K] @ B[K,N] + bias[N]
// Block tile 128x128, BK=16, 256 threads (8 warps, 2x4), warp tile 64x32.
// mma.sync.m16n8k8 tf32. Smem holds FRAGMENT-SHUFFLED tiles so each thread's
// A fragment is one LDS.128 and each B fragment one LDS.64 (conflict-free).
// Requires M%128==0, N%128==0, K%16==0.
// ============================================================================

__device__ __forceinline__ uint32_t f2tf32(float x) {
    uint32_t r;
    asm("cvt.rna.tf32.f32 %0, %1;" : "=r"(r) : "f"(x));
    return r;
}

// Scatter one float4 of the A tile (row arow, cols cbase..cbase+3 of 16)
// into fragment layout: [mt(8)][ks(2)][thread(32)][reg(4)]
__device__ __forceinline__ void stage_a(uint32_t* dst, float4 v, int lin) {
    const int arow = lin >> 2;
    const int cbase = (lin & 3) * 4;
    float vv[4] = {v.x, v.y, v.z, v.w};
#pragma unroll
    for (int u = 0; u < 4; u++) {
        int j  = cbase + u;
        int mt = arow >> 4, rr = arow & 15;
        int ks = j >> 3,    cc = j & 7;
        int t   = (rr & 7) * 4 + (cc & 3);
        int reg = (rr >> 3) + 2 * (cc >> 2);
        dst[((mt * 2 + ks) * 32 + t) * 4 + reg] = f2tf32(vv[u]);
    }
}

// Scatter one float4 of the B tile (row brow = k, cols j..j+3 of 128)
// into fragment layout: [nt(16)][ks(2)][thread(32)][reg(2)]
__device__ __forceinline__ void stage_b(uint32_t* dst, float4 v, int lin) {
    const int brow = lin >> 5;
    const int cbase = (lin & 31) * 4;
    float vv[4] = {v.x, v.y, v.z, v.w};
#pragma unroll
    for (int u = 0; u < 4; u++) {
        int j  = cbase + u;
        int nt = j >> 3, cc = j & 7;
        int ks = brow >> 3, kk = brow & 7;
        int t   = cc * 4 + (kk & 3);
        int reg = kk >> 2;
        dst[((nt * 2 + ks) * 32 + t) * 2 + reg] = f2tf32(vv[u]);
    }
}

__global__ __launch_bounds__(256) void tf32_gemm_bias(
    const float* __restrict__ A, const float* __restrict__ B,
    const float* __restrict__ bias, float* __restrict__ C,
    int M, int N, int K)
{
    __shared__ __align__(16) uint32_t Af[2][2048];  // 8KB each buffer
    __shared__ __align__(16) uint32_t Bf[2][2048];

    const int tid  = threadIdx.x;
    const int lane = tid & 31;
    const int wid  = tid >> 5;
    const int warp_m = wid >> 2;   // 0..1  (64 rows each)
    const int warp_n = wid & 3;    // 0..3  (32 cols each)
    const int bx = blockIdx.x;
    const int by = blockIdx.y;

    float c[4][4][4];
#pragma unroll
    for (int i = 0; i < 4; i++)
#pragma unroll
        for (int j = 0; j < 4; j++)
#pragma unroll
            for (int r = 0; r < 4; r++) c[i][j][r] = 0.f;

    // gmem load indices (two float4 each for A and B per thread)
    const int linA0 = tid, linA1 = 256 + tid;   // A: 128 rows x 4 float4
    const int linB0 = tid, linB1 = 256 + tid;   // B: 16 rows x 32 float4
    const int a_row0 = linA0 >> 2, a_c0 = (linA0 & 3) * 4;
    const int a_row1 = linA1 >> 2, a_c1 = (linA1 & 3) * 4;
    const int b_row0 = linB0 >> 5, b_c0 = (linB0 & 31) * 4;
    const int b_row1 = linB1 >> 5, b_c1 = (linB1 & 31) * 4;

    const float* Ab = A + (size_t)(by * 128) * K;
    const float* Bb = B + bx * 128;

    // prologue: tile 0 -> buffer 0
    {
        float4 a0 = *(const float4*)(Ab + (size_t)a_row0 * K + a_c0);
        float4 a1 = *(const float4*)(Ab + (size_t)a_row1 * K + a_c1);
        float4 b0 = *(const float4*)(Bb + (size_t)b_row0 * N + b_c0);
        float4 b1 = *(const float4*)(Bb + (size_t)b_row1 * N + b_c1);
        stage_a(Af[0], a0, linA0);
        stage_a(Af[0], a1, linA1);
        stage_b(Bf[0], b0, linB0);
        stage_b(Bf[0], b1, linB1);
    }
    __syncthreads();

    int buf = 0;
    for (int k0 = 0; k0 < K; k0 += 16) {
        const int kn = k0 + 16;
        const bool more = (kn < K);
        float4 na0, na1, nb0, nb1;
        if (more) {
            na0 = *(const float4*)(Ab + (size_t)a_row0 * K + kn + a_c0);
            na1 = *(const float4*)(Ab + (size_t)a_row1 * K + kn + a_c1);
            nb0 = *(const float4*)(Bb + (size_t)(kn + b_row0) * N + b_c0);
            nb1 = *(const float4*)(Bb + (size_t)(kn + b_row1) * N + b_c1);
        }

#pragma unroll
        for (int ks = 0; ks < 2; ks++) {
            uint4 a[4];
            uint2 b[4];
#pragma unroll
            for (int mt = 0; mt < 4; mt++)
                a[mt] = *(const uint4*)&Af[buf][(((warp_m * 4 + mt) * 2 + ks) * 32 + lane) * 4];
#pragma unroll
            for (int nt = 0; nt < 4; nt++)
                b[nt] = *(const uint2*)&Bf[buf][(((warp_n * 4 + nt) * 2 + ks) * 32 + lane) * 2];
#pragma unroll
            for (int mt = 0; mt < 4; mt++)
#pragma unroll
                for (int nt = 0; nt < 4; nt++) {
                    asm volatile(
                        "mma.sync.aligned.m16n8k8.row.col.f32.tf32.tf32.f32 "
                        "{%0,%1,%2,%3},{%4,%5,%6,%7},{%8,%9},{%0,%1,%2,%3};"
                        : "+f"(c[mt][nt][0]), "+f"(c[mt][nt][1]),
                          "+f"(c[mt][nt][2]), "+f"(c[mt][nt][3])
                        : "r"(a[mt].x), "r"(a[mt].y), "r"(a[mt].z), "r"(a[mt].w),
                          "r"(b[nt].x), "r"(b[nt].y));
                }
        }

        if (more) {
            const int nb = buf ^ 1;
            stage_a(Af[nb], na0, linA0);
            stage_a(Af[nb], na1, linA1);
            stage_b(Bf[nb], nb0, linB0);
            stage_b(Bf[nb], nb1, linB1);
            __syncthreads();
            buf = nb;
        }
    }

    // epilogue
#pragma unroll
    for (int mt = 0; mt < 4; mt++) {
        int gr = by * 128 + warp_m * 64 + mt * 16 + (lane >> 2);
#pragma unroll
        for (int nt = 0; nt < 4; nt++) {
            int gc = bx * 128 + warp_n * 32 + nt * 8 + (lane & 3) * 2;
            float bx0 = bias[gc], bx1 = bias[gc + 1];
            float2 r0 = {c[mt][nt][0] + bx0, c[mt][nt][1] + bx1};
            float2 r1 = {c[mt][nt][2] + bx0, c[mt][nt][3] + bx1};
            *(float2*)(C + (size_t)gr * N + gc) = r0;
            *(float2*)(C + (size_t)(gr + 8) * N + gc) = r1;
        }
    }
}

// ---------------- fused per-head LayerNorm + RoPE ---------------------------
__global__ void ln_rope_kernel(float* __restrict__ buf,
                               const float* __restrict__ gamma,
                               const float* __restrict__ beta,
                               int heads, int seq)
{
    int row = blockIdx.x * blockDim.y + threadIdx.y;
    int total = seq * heads;
    if (row >= total) return;
    int s = row / heads;
    int lane = threadIdx.x;

    float* p = buf + (size_t)row * HEAD_DIM;
    float x0 = p[lane];
    float x1 = p[lane + 32];

    float sum = x0 + x1;
    float sq  = x0 * x0 + x1 * x1;
#pragma unroll
    for (int o = 16; o > 0; o >>= 1) {
        sum += __shfl_xor_sync(0xFFFFFFFFu, sum, o);
        sq  += __shfl_xor_sync(0xFFFFFFFFu, sq,  o);
    }
    float mean = sum * (1.0f / 64.0f);
    float var  = sq * (1.0f / 64.0f) - mean * mean;
    float inv  = rsqrtf(var + 1e-5f);

    float y0 = (x0 - mean) * inv * gamma[lane]      + beta[lane];
    float y1 = (x1 - mean) * inv * gamma[lane + 32] + beta[lane + 32];

    float freq = powf(10000.0f, -(float)lane * (1.0f / 32.0f));
    float ang  = (float)s * freq;
    float c, sn;
    sincosf(ang, &sn, &c);

    p[lane]      = y0 * c - y1 * sn;
    p[lane + 32] = y1 * c + y0 * sn;
}

// ---------------- flash attention (fp32, non-causal, GQA) -------------------
#define BQ 64
#define BKT 32

__global__ __launch_bounds__(256) void attn_kernel(
    const float* __restrict__ q, const float* __restrict__ k,
    const float* __restrict__ v, float* __restrict__ out)
{
    __shared__ float Qs[BQ][HEAD_DIM + 1];
    __shared__ float Ks[BKT][HEAD_DIM + 1];
    __shared__ float Vs[BKT][HEAD_DIM + 1];
    __shared__ float Ps[BQ][BKT + 1];

    const int h  = blockIdx.y;         // q head
    const int g  = h >> 2;             // kv head
    const int q0 = blockIdx.x * BQ;
    const int tid = threadIdx.x;
    const int row = tid >> 2;          // 0..63
    const int cseg = tid & 3;
    const int cs = cseg * 16;
    const int j0 = cseg * 8;

    for (int i = tid; i < BQ * HEAD_DIM; i += 256) {
        int r = i >> 6, c = i & 63;
        Qs[r][c] = q[(size_t)(q0 + r) * HIDDEN + h * HEAD_DIM + c];
    }

    float m = -1e30f, l = 0.f;
    float acc[16];
#pragma unroll
    for (int d = 0; d < 16; d++) acc[d] = 0.f;

    for (int k0 = 0; k0 < SEQ; k0 += BKT) {
        for (int i = tid; i < BKT * HEAD_DIM; i += 256) {
            int r = i >> 6, c = i & 63;
            Ks[r][c] = k[(size_t)(k0 + r) * KV_DIM + g * HEAD_DIM + c];
            Vs[r][c] = v[(size_t)(k0 + r) * KV_DIM + g * HEAD_DIM + c];
        }
        __syncthreads();

        float sc[8];
#pragma unroll
        for (int jj = 0; jj < 8; jj++) sc[jj] = 0.f;
#pragma unroll 16
        for (int d = 0; d < HEAD_DIM; d++) {
            float qd = Qs[row][d];
#pragma unroll
            for (int jj = 0; jj < 8; jj++)
                sc[jj] = fmaf(qd, Ks[j0 + jj][d], sc[jj]);
        }
#pragma unroll
        for (int jj = 0; jj < 8; jj++) sc[jj] *= 0.125f;

        float mp = sc[0];
#pragma unroll
        for (int jj = 1; jj < 8; jj++) mp = fmaxf(mp, sc[jj]);
        mp = fmaxf(mp, __shfl_xor_sync(0xFFFFFFFFu, mp, 1));
        mp = fmaxf(mp, __shfl_xor_sync(0xFFFFFFFFu, mp, 2));
        float mt = fmaxf(m, mp);
        float alpha = __expf(m - mt);
        m = mt;

        float lp = 0.f;
#pragma unroll
        for (int jj = 0; jj < 8; jj++) {
            float pv = __expf(sc[jj] - mt);
            lp += pv;
            Ps[row][j0 + jj] = pv;
        }
        lp += __shfl_xor_sync(0xFFFFFFFFu, lp, 1);
        lp += __shfl_xor_sync(0xFFFFFFFFu, lp, 2);
        l = l * alpha + lp;

#pragma unroll
        for (int d = 0; d < 16; d++) acc[d] *= alpha;
        __syncwarp();

#pragma unroll 4
        for (int j = 0; j < BKT; j++) {
            float pv = Ps[row][j];
#pragma unroll
            for (int d = 0; d < 16; d++)
                acc[d] = fmaf(pv, Vs[j][cs + d], acc[d]);
        }
        __syncthreads();
    }

    float invl = 1.0f / l;
#pragma unroll
    for (int d = 0; d < 16; d++)
        out[(size_t)(q0 + row) * HIDDEN + h * HEAD_DIM + cs + d] = acc[d] * invl;
}

// ---------------- launch --------------------------------------------------
extern "C" void kernel_launch(void* const* d_in, const int* in_sizes, int n_in,
                              void* d_out, int out_size)
{
    const float* x   = (const float*)d_in[0];
    const float* Wq  = (const float*)d_in[1];
    const float* bq  = (const float*)d_in[2];
    const float* Wk  = (const float*)d_in[3];
    const float* bk  = (const float*)d_in[4];
    const float* Wv  = (const float*)d_in[5];
    const float* bv  = (const float*)d_in[6];
    const float* Wo  = (const float*)d_in[7];
    const float* bo  = (const float*)d_in[8];
    const float* q_g = (const float*)d_in[9];
    const float* q_b = (const float*)d_in[10];
    const float* k_g = (const float*)d_in[11];
    const float* k_b = (const float*)d_in[12];
    float* out = (float*)d_out;

    void *pq, *pk, *pv, *po;
    cudaGetSymbolAddress(&pq, g_q);
    cudaGetSymbolAddress(&pk, g_k);
    cudaGetSymbolAddress(&pv, g_v);
    cudaGetSymbolAddress(&po, g_o);
    float* fq = (float*)pq;
    float* fk = (float*)pk;
    float* fv = (float*)pv;
    float* fo = (float*)po;

    // Q/K/V projections (tf32 tensor cores)
    {
        dim3 grid(HIDDEN / 128, SEQ / 128);
        tf32_gemm_bias<<<grid, 256>>>(x, Wq, bq, fq, SEQ, HIDDEN, HIDDEN);
    }
    {
        dim3 grid(KV_DIM / 128, SEQ / 128);
        tf32_gemm_bias<<<grid, 256>>>(x, Wk, bk, fk, SEQ, KV_DIM, HIDDEN);
        tf32_gemm_bias<<<grid, 256>>>(x, Wv, bv, fv, SEQ, KV_DIM, HIDDEN);
    }

    // per-head LN + RoPE
    {
        dim3 blk(32, 4);
        int rows_q = SEQ * N_HEADS;
        int rows_k = SEQ * N_KV;
        ln_rope_kernel<<<(rows_q + 3) / 4, blk>>>(fq, q_g, q_b, N_HEADS, SEQ);
        ln_rope_kernel<<<(rows_k + 3) / 4, blk>>>(fk, k_g, k_b, N_KV, SEQ);
    }

    // attention
    {
        dim3 grid(SEQ / BQ, N_HEADS);
        attn_kernel<<<grid, 256>>>(fq, fk, fv, fo);
    }

    // output projection (tf32 tensor cores)
    {
        dim3 grid(HIDDEN / 128, SEQ / 128);
        tf32_gemm_bias<<<grid, 256>>>(fo, Wo, bo, out, SEQ, HIDDEN, HIDDEN);
    }
}

// round 4
// speedup vs baseline: 3.1175x; 2.6187x over previous
#include <cuda_runtime.h>
#include <cuda_bf16.h>
#include <math.h>
#include <stdint.h>

// ---------------- problem constants ----------------
#define SEQ      2048
#define HIDDEN   2048
#define N_HEADS  32
#define N_KV     8
#define HEAD_DIM 64
#define KV_DIM   (N_KV * HEAD_DIM)   // 512

// ---------------- scratch (static device globals; no allocs allowed) -------
__device__ float g_q[SEQ * HIDDEN];   // [s, 32, 64]
__device__ float g_k[SEQ * KV_DIM];   // [s, 8, 64]
__device__ float g_v[SEQ * KV_DIM];   // [s, 8, 64]
__device__ float g_o[SEQ * HIDDEN];   // attention output [s, 32*64]

__device__ __forceinline__ uint32_t f2tf32(float x) {
    uint32_t r;
    asm("cvt.rna.tf32.f32 %0, %1;" : "=r"(r) : "f"(x));
    return r;
}

__device__ __forceinline__ void mma_tf32(float c[4], const uint32_t a[4], const uint32_t b[2]) {
    asm volatile(
        "mma.sync.aligned.m16n8k8.row.col.f32.tf32.tf32.f32 "
        "{%0,%1,%2,%3},{%4,%5,%6,%7},{%8,%9},{%0,%1,%2,%3};"
        : "+f"(c[0]), "+f"(c[1]), "+f"(c[2]), "+f"(c[3])
        : "r"(a[0]), "r"(a[1]), "r"(a[2]), "r"(a[3]), "r"(b[0]), "r"(b[1]));
}

// ============================================================================
// TF32 tensor-core GEMM (unchanged from R3): C = A @ B + bias
// ============================================================================
__device__ __forceinline__ void stage_a(uint32_t* dst, float4 v, int lin) {
    const int arow = lin >> 2;
    const int cbase = (lin & 3) * 4;
    float vv[4] = {v.x, v.y, v.z, v.w};
#pragma unroll
    for (int u = 0; u < 4; u++) {
        int j  = cbase + u;
        int mt = arow >> 4, rr = arow & 15;
        int ks = j >> 3,    cc = j & 7;
        int t   = (rr & 7) * 4 + (cc & 3);
        int reg = (rr >> 3) + 2 * (cc >> 2);
        dst[((mt * 2 + ks) * 32 + t) * 4 + reg] = f2tf32(vv[u]);
    }
}

__device__ __forceinline__ void stage_b(uint32_t* dst, float4 v, int lin) {
    const int brow = lin >> 5;
    const int cbase = (lin & 31) * 4;
    float vv[4] = {v.x, v.y, v.z, v.w};
#pragma unroll
    for (int u = 0; u < 4; u++) {
        int j  = cbase + u;
        int nt = j >> 3, cc = j & 7;
        int ks = brow >> 3, kk = brow & 7;
        int t   = cc * 4 + (kk & 3);
        int reg = kk >> 2;
        dst[((nt * 2 + ks) * 32 + t) * 2 + reg] = f2tf32(vv[u]);
    }
}

__global__ __launch_bounds__(256) void tf32_gemm_bias(
    const float* __restrict__ A, const float* __restrict__ B,
    const float* __restrict__ bias, float* __restrict__ C,
    int M, int N, int K)
{
    __shared__ __align__(16) uint32_t Af[2][2048];
    __shared__ __align__(16) uint32_t Bf[2][2048];

    const int tid  = threadIdx.x;
    const int lane = tid & 31;
    const int wid  = tid >> 5;
    const int warp_m = wid >> 2;
    const int warp_n = wid & 3;
    const int bx = blockIdx.x;
    const int by = blockIdx.y;

    float c[4][4][4];
#pragma unroll
    for (int i = 0; i < 4; i++)
#pragma unroll
        for (int j = 0; j < 4; j++)
#pragma unroll
            for (int r = 0; r < 4; r++) c[i][j][r] = 0.f;

    const int linA0 = tid, linA1 = 256 + tid;
    const int linB0 = tid, linB1 = 256 + tid;
    const int a_row0 = linA0 >> 2, a_c0 = (linA0 & 3) * 4;
    const int a_row1 = linA1 >> 2, a_c1 = (linA1 & 3) * 4;
    const int b_row0 = linB0 >> 5, b_c0 = (linB0 & 31) * 4;
    const int b_row1 = linB1 >> 5, b_c1 = (linB1 & 31) * 4;

    const float* Ab = A + (size_t)(by * 128) * K;
    const float* Bb = B + bx * 128;

    {
        float4 a0 = *(const float4*)(Ab + (size_t)a_row0 * K + a_c0);
        float4 a1 = *(const float4*)(Ab + (size_t)a_row1 * K + a_c1);
        float4 b0 = *(const float4*)(Bb + (size_t)b_row0 * N + b_c0);
        float4 b1 = *(const float4*)(Bb + (size_t)b_row1 * N + b_c1);
        stage_a(Af[0], a0, linA0);
        stage_a(Af[0], a1, linA1);
        stage_b(Bf[0], b0, linB0);
        stage_b(Bf[0], b1, linB1);
    }
    __syncthreads();

    int buf = 0;
    for (int k0 = 0; k0 < K; k0 += 16) {
        const int kn = k0 + 16;
        const bool more = (kn < K);
        float4 na0, na1, nb0, nb1;
        if (more) {
            na0 = *(const float4*)(Ab + (size_t)a_row0 * K + kn + a_c0);
            na1 = *(const float4*)(Ab + (size_t)a_row1 * K + kn + a_c1);
            nb0 = *(const float4*)(Bb + (size_t)(kn + b_row0) * N + b_c0);
            nb1 = *(const float4*)(Bb + (size_t)(kn + b_row1) * N + b_c1);
        }

#pragma unroll
        for (int ks = 0; ks < 2; ks++) {
            uint4 a[4];
            uint2 b[4];
#pragma unroll
            for (int mt = 0; mt < 4; mt++)
                a[mt] = *(const uint4*)&Af[buf][(((warp_m * 4 + mt) * 2 + ks) * 32 + lane) * 4];
#pragma unroll
            for (int nt = 0; nt < 4; nt++)
                b[nt] = *(const uint2*)&Bf[buf][(((warp_n * 4 + nt) * 2 + ks) * 32 + lane) * 2];
#pragma unroll
            for (int mt = 0; mt < 4; mt++)
#pragma unroll
                for (int nt = 0; nt < 4; nt++) {
                    uint32_t ar[4] = {a[mt].x, a[mt].y, a[mt].z, a[mt].w};
                    uint32_t br[2] = {b[nt].x, b[nt].y};
                    mma_tf32(c[mt][nt], ar, br);
                }
        }

        if (more) {
            const int nb = buf ^ 1;
            stage_a(Af[nb], na0, linA0);
            stage_a(Af[nb], na1, linA1);
            stage_b(Bf[nb], nb0, linB0);
            stage_b(Bf[nb], nb1, linB1);
            __syncthreads();
            buf = nb;
        }
    }

#pragma unroll
    for (int mt = 0; mt < 4; mt++) {
        int gr = by * 128 + warp_m * 64 + mt * 16 + (lane >> 2);
#pragma unroll
        for (int nt = 0; nt < 4; nt++) {
            int gc = bx * 128 + warp_n * 32 + nt * 8 + (lane & 3) * 2;
            float bx0 = bias[gc], bx1 = bias[gc + 1];
            float2 r0 = {c[mt][nt][0] + bx0, c[mt][nt][1] + bx1};
            float2 r1 = {c[mt][nt][2] + bx0, c[mt][nt][3] + bx1};
            *(float2*)(C + (size_t)gr * N + gc) = r0;
            *(float2*)(C + (size_t)(gr + 8) * N + gc) = r1;
        }
    }
}

// ---------------- fused per-head LayerNorm + RoPE ---------------------------
__global__ void ln_rope_kernel(float* __restrict__ buf,
                               const float* __restrict__ gamma,
                               const float* __restrict__ beta,
                               int heads, int seq)
{
    int row = blockIdx.x * blockDim.y + threadIdx.y;
    int total = seq * heads;
    if (row >= total) return;
    int s = row / heads;
    int lane = threadIdx.x;

    float* p = buf + (size_t)row * HEAD_DIM;
    float x0 = p[lane];
    float x1 = p[lane + 32];

    float sum = x0 + x1;
    float sq  = x0 * x0 + x1 * x1;
#pragma unroll
    for (int o = 16; o > 0; o >>= 1) {
        sum += __shfl_xor_sync(0xFFFFFFFFu, sum, o);
        sq  += __shfl_xor_sync(0xFFFFFFFFu, sq,  o);
    }
    float mean = sum * (1.0f / 64.0f);
    float var  = sq * (1.0f / 64.0f) - mean * mean;
    float inv  = rsqrtf(var + 1e-5f);

    float y0 = (x0 - mean) * inv * gamma[lane]      + beta[lane];
    float y1 = (x1 - mean) * inv * gamma[lane + 32] + beta[lane + 32];

    float freq = powf(10000.0f, -(float)lane * (1.0f / 32.0f));
    float ang  = (float)s * freq;
    float c, sn;
    sincosf(ang, &sn, &c);

    p[lane]      = y0 * c - y1 * sn;
    p[lane + 32] = y1 * c + y0 * sn;
}

// ============================================================================
// Tensor-core flash attention (tf32 mma, non-causal, GQA)
// Block: one q-head, 64 q-rows. 4 warps; warp w owns rows [q0+16w, q0+16w+16).
// KV tiles of 32. Smem strides chosen for conflict-free fragment access.
// ============================================================================
#define AT_BK 32
#define KS_STRIDE 68
#define VS_STRIDE 72
#define PS_STRIDE 36

__global__ __launch_bounds__(128) void attn_mma_kernel(
    const float* __restrict__ q, const float* __restrict__ k,
    const float* __restrict__ v, float* __restrict__ out)
{
    __shared__ uint32_t Ks[AT_BK * KS_STRIDE];          // [row][dim], tf32 bits
    __shared__ uint32_t Vs[AT_BK * VS_STRIDE];          // [row][dim]
    __shared__ __align__(8) uint32_t Ps[4][16 * PS_STRIDE];  // per-warp P tile

    const int h   = blockIdx.y;
    const int g   = h >> 2;
    const int q0  = blockIdx.x * 64;
    const int tid = threadIdx.x;
    const int w   = tid >> 5;
    const int lane = tid & 31;
    const int gid  = lane >> 2;   // group id (row within fragment)
    const int tig  = lane & 3;    // thread in group

    // ---- Q fragments for this warp (rows q0+16w .. +15), all 8 k-steps ----
    uint32_t qf[8][4];
    {
        const float* qp = q + (size_t)(q0 + w * 16) * HIDDEN + h * HEAD_DIM;
#pragma unroll
        for (int ks = 0; ks < 8; ks++) {
            qf[ks][0] = f2tf32(qp[(size_t)gid       * HIDDEN + ks * 8 + tig]);
            qf[ks][1] = f2tf32(qp[(size_t)(gid + 8) * HIDDEN + ks * 8 + tig]);
            qf[ks][2] = f2tf32(qp[(size_t)gid       * HIDDEN + ks * 8 + tig + 4]);
            qf[ks][3] = f2tf32(qp[(size_t)(gid + 8) * HIDDEN + ks * 8 + tig + 4]);
        }
    }

    float o[8][4];
#pragma unroll
    for (int nt = 0; nt < 8; nt++)
#pragma unroll
        for (int r = 0; r < 4; r++) o[nt][r] = 0.f;
    float m0 = -1e30f, m1 = -1e30f, l0 = 0.f, l1 = 0.f;

    // K/V tile load mapping: 512 float4 per tile each; 4 per thread.
    const int f4i0 = tid;         // + i*128
    const float* kbase = k + g * HEAD_DIM;
    const float* vbase = v + g * HEAD_DIM;

    // prefetch tile 0
    float4 kf[4], vf[4];
#pragma unroll
    for (int i = 0; i < 4; i++) {
        int f4 = f4i0 + i * 128;
        int row = f4 >> 4, c4 = (f4 & 15) * 4;
        kf[i] = *(const float4*)(kbase + (size_t)row * KV_DIM + c4);
        vf[i] = *(const float4*)(vbase + (size_t)row * KV_DIM + c4);
    }

    const int NT = SEQ / AT_BK;
    for (int t = 0; t < NT; t++) {
        // stage current tile to smem (cvt to tf32 bits)
#pragma unroll
        for (int i = 0; i < 4; i++) {
            int f4 = f4i0 + i * 128;
            int row = f4 >> 4, c4 = (f4 & 15) * 4;
            uint32_t* kd = &Ks[row * KS_STRIDE + c4];
            kd[0] = f2tf32(kf[i].x); kd[1] = f2tf32(kf[i].y);
            kd[2] = f2tf32(kf[i].z); kd[3] = f2tf32(kf[i].w);
            uint32_t* vd = &Vs[row * VS_STRIDE + c4];
            vd[0] = f2tf32(vf[i].x); vd[1] = f2tf32(vf[i].y);
            vd[2] = f2tf32(vf[i].z); vd[3] = f2tf32(vf[i].w);
        }
        __syncthreads();

        // prefetch next tile
        if (t + 1 < NT) {
#pragma unroll
            for (int i = 0; i < 4; i++) {
                int f4 = f4i0 + i * 128;
                int row = f4 >> 4, c4 = (f4 & 15) * 4;
                size_t off = (size_t)((t + 1) * AT_BK + row) * KV_DIM + c4;
                kf[i] = *(const float4*)(kbase + off);
                vf[i] = *(const float4*)(vbase + off);
            }
        }

        // ---- scores: S[16][32] = Q @ K^T (4 n-tiles) ----
        float s[4][4];
#pragma unroll
        for (int nt = 0; nt < 4; nt++)
#pragma unroll
            for (int r = 0; r < 4; r++) s[nt][r] = 0.f;
#pragma unroll
        for (int ks = 0; ks < 8; ks++) {
#pragma unroll
            for (int nt = 0; nt < 4; nt++) {
                uint32_t b[2];
                const uint32_t* kp = &Ks[(nt * 8 + gid) * KS_STRIDE + ks * 8 + tig];
                b[0] = kp[0];
                b[1] = kp[4];
                mma_tf32(s[nt], qf[ks], b);
            }
        }

        // ---- online softmax (rows gid and gid+8) ----
#pragma unroll
        for (int nt = 0; nt < 4; nt++)
#pragma unroll
            for (int r = 0; r < 4; r++) s[nt][r] *= 0.125f;

        float mr0 = s[0][0], mr1 = s[0][2];
#pragma unroll
        for (int nt = 0; nt < 4; nt++) {
            mr0 = fmaxf(mr0, fmaxf(s[nt][0], s[nt][1]));
            mr1 = fmaxf(mr1, fmaxf(s[nt][2], s[nt][3]));
        }
        mr0 = fmaxf(mr0, __shfl_xor_sync(0xFFFFFFFFu, mr0, 1));
        mr0 = fmaxf(mr0, __shfl_xor_sync(0xFFFFFFFFu, mr0, 2));
        mr1 = fmaxf(mr1, __shfl_xor_sync(0xFFFFFFFFu, mr1, 1));
        mr1 = fmaxf(mr1, __shfl_xor_sync(0xFFFFFFFFu, mr1, 2));

        float mn0 = fmaxf(m0, mr0), mn1 = fmaxf(m1, mr1);
        float a0 = __expf(m0 - mn0), a1 = __expf(m1 - mn1);
        m0 = mn0; m1 = mn1;

        float lp0 = 0.f, lp1 = 0.f;
        uint32_t* Pw = Ps[w];
#pragma unroll
        for (int nt = 0; nt < 4; nt++) {
            float p00 = __expf(s[nt][0] - mn0);
            float p01 = __expf(s[nt][1] - mn0);
            float p10 = __expf(s[nt][2] - mn1);
            float p11 = __expf(s[nt][3] - mn1);
            lp0 += p00 + p01;
            lp1 += p10 + p11;
            uint32_t* d0 = &Pw[gid * PS_STRIDE + nt * 8 + 2 * tig];
            d0[0] = f2tf32(p00); d0[1] = f2tf32(p01);
            uint32_t* d1 = &Pw[(gid + 8) * PS_STRIDE + nt * 8 + 2 * tig];
            d1[0] = f2tf32(p10); d1[1] = f2tf32(p11);
        }
        lp0 += __shfl_xor_sync(0xFFFFFFFFu, lp0, 1);
        lp0 += __shfl_xor_sync(0xFFFFFFFFu, lp0, 2);
        lp1 += __shfl_xor_sync(0xFFFFFFFFu, lp1, 1);
        lp1 += __shfl_xor_sync(0xFFFFFFFFu, lp1, 2);
        l0 = l0 * a0 + lp0;
        l1 = l1 * a1 + lp1;

        // rescale O
#pragma unroll
        for (int nt = 0; nt < 8; nt++) {
            o[nt][0] *= a0; o[nt][1] *= a0;
            o[nt][2] *= a1; o[nt][3] *= a1;
        }
        __syncwarp();

        // ---- O += P @ V ----
#pragma unroll
        for (int kj = 0; kj < 4; kj++) {
            uint32_t a[4];
            a[0] = Pw[gid * PS_STRIDE + kj * 8 + tig];
            a[1] = Pw[(gid + 8) * PS_STRIDE + kj * 8 + tig];
            a[2] = Pw[gid * PS_STRIDE + kj * 8 + tig + 4];
            a[3] = Pw[(gid + 8) * PS_STRIDE + kj * 8 + tig + 4];
#pragma unroll
            for (int nt = 0; nt < 8; nt++) {
                uint32_t b[2];
                const uint32_t* vp = &Vs[(kj * 8 + tig) * VS_STRIDE + nt * 8 + gid];
                b[0] = vp[0];
                b[1] = vp[4 * VS_STRIDE];
                mma_tf32(o[nt], a, b);
            }
        }
        __syncthreads();
    }

    // ---- write out ----
    float il0 = 1.0f / l0, il1 = 1.0f / l1;
    float* op0 = out + (size_t)(q0 + w * 16 + gid) * HIDDEN + h * HEAD_DIM;
    float* op1 = out + (size_t)(q0 + w * 16 + gid + 8) * HIDDEN + h * HEAD_DIM;
#pragma unroll
    for (int nt = 0; nt < 8; nt++) {
        int col = nt * 8 + 2 * tig;
        float2 r0 = {o[nt][0] * il0, o[nt][1] * il0};
        float2 r1 = {o[nt][2] * il1, o[nt][3] * il1};
        *(float2*)(op0 + col) = r0;
        *(float2*)(op1 + col) = r1;
    }
}

// ---------------- launch --------------------------------------------------
extern "C" void kernel_launch(void* const* d_in, const int* in_sizes, int n_in,
                              void* d_out, int out_size)
{
    const float* x   = (const float*)d_in[0];
    const float* Wq  = (const float*)d_in[1];
    const float* bq  = (const float*)d_in[2];
    const float* Wk  = (const float*)d_in[3];
    const float* bk  = (const float*)d_in[4];
    const float* Wv  = (const float*)d_in[5];
    const float* bv  = (const float*)d_in[6];
    const float* Wo  = (const float*)d_in[7];
    const float* bo  = (const float*)d_in[8];
    const float* q_g = (const float*)d_in[9];
    const float* q_b = (const float*)d_in[10];
    const float* k_g = (const float*)d_in[11];
    const float* k_b = (const float*)d_in[12];
    float* out = (float*)d_out;

    void *pq, *pk, *pv, *po;
    cudaGetSymbolAddress(&pq, g_q);
    cudaGetSymbolAddress(&pk, g_k);
    cudaGetSymbolAddress(&pv, g_v);
    cudaGetSymbolAddress(&po, g_o);
    float* fq = (float*)pq;
    float* fk = (float*)pk;
    float* fv = (float*)pv;
    float* fo = (float*)po;

    // Q/K/V projections (tf32 tensor cores)
    {
        dim3 grid(HIDDEN / 128, SEQ / 128);
        tf32_gemm_bias<<<grid, 256>>>(x, Wq, bq, fq, SEQ, HIDDEN, HIDDEN);
    }
    {
        dim3 grid(KV_DIM / 128, SEQ / 128);
        tf32_gemm_bias<<<grid, 256>>>(x, Wk, bk, fk, SEQ, KV_DIM, HIDDEN);
        tf32_gemm_bias<<<grid, 256>>>(x, Wv, bv, fv, SEQ, KV_DIM, HIDDEN);
    }

    // per-head LN + RoPE
    {
        dim3 blk(32, 4);
        int rows_q = SEQ * N_HEADS;
        int rows_k = SEQ * N_KV;
        ln_rope_kernel<<<(rows_q + 3) / 4, blk>>>(fq, q_g, q_b, N_HEADS, SEQ);
        ln_rope_kernel<<<(rows_k + 3) / 4, blk>>>(fk, k_g, k_b, N_KV, SEQ);
    }

    // attention (tensor cores)
    {
        dim3 grid(SEQ / 64, N_HEADS);
        attn_mma_kernel<<<grid, 128>>>(fq, fk, fv, fo);
    }

    // output projection (tf32 tensor cores)
    {
        dim3 grid(HIDDEN / 128, SEQ / 128);
        tf32_gemm_bias<<<grid, 256>>>(fo, Wo, bo, out, SEQ, HIDDEN, HIDDEN);
    }
}

// round 5
// speedup vs baseline: 7.3405x; 2.3546x over previous
#include <cuda_runtime.h>
#include <cuda_bf16.h>
#include <math.h>
#include <stdint.h>

// ---------------- problem constants ----------------
#define SEQ      2048
#define HIDDEN   2048
#define N_HEADS  32
#define N_KV     8
#define HEAD_DIM 64
#define KV_DIM   (N_KV * HEAD_DIM)   // 512

// ---------------- scratch (static device globals; no allocs allowed) -------
__device__ float g_q[SEQ * HIDDEN];   // [s, 32, 64]
__device__ float g_k[SEQ * KV_DIM];   // [s, 8, 64]
__device__ float g_v[SEQ * KV_DIM];   // [s, 8, 64]

// fragment-staged operands (tf32 bits). Tile = 2048 words (8KB).
// A layout: [M/128][K/16][2048] ; B layout: [K/16][N/128][2048]
__device__ uint32_t g_xa[(SEQ / 128) * (HIDDEN / 16) * 2048];   // 16 MB
__device__ uint32_t g_wq[(HIDDEN / 16) * (HIDDEN / 128) * 2048];
__device__ uint32_t g_wk[(HIDDEN / 16) * (KV_DIM / 128) * 2048];
__device__ uint32_t g_wv[(HIDDEN / 16) * (KV_DIM / 128) * 2048];
__device__ uint32_t g_wo[(HIDDEN / 16) * (HIDDEN / 128) * 2048];
__device__ uint32_t g_oa[(SEQ / 128) * (HIDDEN / 16) * 2048];   // attn out, staged

__device__ __forceinline__ uint32_t f2tf32(float x) {
    uint32_t r;
    asm("cvt.rna.tf32.f32 %0, %1;" : "=r"(r) : "f"(x));
    return r;
}

__device__ __forceinline__ void mma_tf32(float c[4], const uint32_t a[4], const uint32_t b[2]) {
    asm volatile(
        "mma.sync.aligned.m16n8k8.row.col.f32.tf32.tf32.f32 "
        "{%0,%1,%2,%3},{%4,%5,%6,%7},{%8,%9},{%0,%1,%2,%3};"
        : "+f"(c[0]), "+f"(c[1]), "+f"(c[2]), "+f"(c[3])
        : "r"(a[0]), "r"(a[1]), "r"(a[2]), "r"(a[3]), "r"(b[0]), "r"(b[1]));
}

__device__ __forceinline__ uint32_t smem_u32(const void* p) {
    return (uint32_t)__cvta_generic_to_shared(p);
}
__device__ __forceinline__ void cp_async16(void* smem, const void* gmem) {
    asm volatile("cp.async.cg.shared.global [%0], [%1], 16;"
                 :: "r"(smem_u32(smem)), "l"(gmem));
}
#define CP_COMMIT() asm volatile("cp.async.commit_group;")
#define CP_WAIT2()  asm volatile("cp.async.wait_group 2;")

// ---------------- fragment scatter maps (same layout as R3/R4 GEMM) --------
// A tile 128x16 -> [mt(8)][ks(2)][thread(32)][reg(4)]
__device__ __forceinline__ void stage_a(uint32_t* dst, float4 v, int lin) {
    const int arow = lin >> 2;
    const int cbase = (lin & 3) * 4;
    float vv[4] = {v.x, v.y, v.z, v.w};
#pragma unroll
    for (int u = 0; u < 4; u++) {
        int j  = cbase + u;
        int mt = arow >> 4, rr = arow & 15;
        int ks = j >> 3,    cc = j & 7;
        int t   = (rr & 7) * 4 + (cc & 3);
        int reg = (rr >> 3) + 2 * (cc >> 2);
        dst[((mt * 2 + ks) * 32 + t) * 4 + reg] = f2tf32(vv[u]);
    }
}
// B tile 16x128 -> [nt(16)][ks(2)][thread(32)][reg(2)]
__device__ __forceinline__ void stage_b(uint32_t* dst, float4 v, int lin) {
    const int brow = lin >> 5;
    const int cbase = (lin & 31) * 4;
    float vv[4] = {v.x, v.y, v.z, v.w};
#pragma unroll
    for (int u = 0; u < 4; u++) {
        int j  = cbase + u;
        int nt = j >> 3, cc = j & 7;
        int ks = brow >> 3, kk = brow & 7;
        int t   = cc * 4 + (kk & 3);
        int reg = kk >> 2;
        dst[((nt * 2 + ks) * 32 + t) * 2 + reg] = f2tf32(vv[u]);
    }
}

// ---------------- pre-shuffle kernels ---------------------------------------
__global__ __launch_bounds__(256) void shuffle_a_kernel(
    const float* __restrict__ A, uint32_t* __restrict__ Af, int M, int K)
{
    __shared__ __align__(16) uint32_t buf[2048];
    const int kt = blockIdx.x, by = blockIdx.y;
    const int Kt = K / 16;
    const int tid = threadIdx.x;
    const float* Ab = A + (size_t)(by * 128) * K + kt * 16;
#pragma unroll
    for (int i = 0; i < 2; i++) {
        int lin = tid + i * 256;
        int row = lin >> 2, c4 = (lin & 3) * 4;
        float4 v = *(const float4*)(Ab + (size_t)row * K + c4);
        stage_a(buf, v, lin);
    }
    __syncthreads();
    uint32_t* dst = Af + ((size_t)by * Kt + kt) * 2048;
    *(uint4*)(dst + tid * 4)        = *(const uint4*)(buf + tid * 4);
    *(uint4*)(dst + 1024 + tid * 4) = *(const uint4*)(buf + 1024 + tid * 4);
}

__global__ __launch_bounds__(256) void shuffle_b_kernel(
    const float* __restrict__ B, uint32_t* __restrict__ Bf, int K, int N)
{
    __shared__ __align__(16) uint32_t buf[2048];
    const int bx = blockIdx.x, kt = blockIdx.y;
    const int NB = N / 128;
    const int tid = threadIdx.x;
    const float* Bb = B + (size_t)(kt * 16) * N + bx * 128;
#pragma unroll
    for (int i = 0; i < 2; i++) {
        int lin = tid + i * 256;
        int brow = lin >> 5, c4 = (lin & 31) * 4;
        float4 v = *(const float4*)(Bb + (size_t)brow * N + c4);
        stage_b(buf, v, lin);
    }
    __syncthreads();
    uint32_t* dst = Bf + ((size_t)kt * NB + bx) * 2048;
    *(uint4*)(dst + tid * 4)        = *(const uint4*)(buf + tid * 4);
    *(uint4*)(dst + 1024 + tid * 4) = *(const uint4*)(buf + 1024 + tid * 4);
}

// ---------------- staged TF32 GEMM: C = A@B + bias --------------------------
// Operands pre-shuffled into fragment layout; 3-stage cp.async pipeline.
__global__ __launch_bounds__(256) void tf32_gemm_staged(
    const uint32_t* __restrict__ Af, const uint32_t* __restrict__ Bf,
    const float* __restrict__ bias, float* __restrict__ C,
    int M, int N, int K)
{
    __shared__ __align__(16) uint32_t As[3][2048];
    __shared__ __align__(16) uint32_t Bs[3][2048];

    const int tid  = threadIdx.x;
    const int lane = tid & 31;
    const int wid  = tid >> 5;
    const int warp_m = wid >> 2;
    const int warp_n = wid & 3;
    const int bx = blockIdx.x;
    const int by = blockIdx.y;
    const int Kt = K / 16;
    const int NB = N / 128;

    const uint32_t* Abase = Af + (size_t)by * Kt * 2048;
    const uint32_t* Bbase = Bf + (size_t)bx * 2048;

    float c[4][4][4];
#pragma unroll
    for (int i = 0; i < 4; i++)
#pragma unroll
        for (int j = 0; j < 4; j++)
#pragma unroll
            for (int r = 0; r < 4; r++) c[i][j][r] = 0.f;

    const int o0 = tid * 4;
    const int o1 = 1024 + tid * 4;

#define GEMM_ISSUE(kt_, s_)                                                  \
    do {                                                                     \
        if ((kt_) < Kt) {                                                    \
            const uint32_t* ag = Abase + (size_t)(kt_) * 2048;               \
            const uint32_t* bg = Bbase + (size_t)(kt_) * NB * 2048;          \
            cp_async16(&As[s_][o0], ag + o0);                                \
            cp_async16(&As[s_][o1], ag + o1);                                \
            cp_async16(&Bs[s_][o0], bg + o0);                                \
            cp_async16(&Bs[s_][o1], bg + o1);                                \
        }                                                                    \
        CP_COMMIT();                                                         \
    } while (0)

    GEMM_ISSUE(0, 0);
    GEMM_ISSUE(1, 1);
    GEMM_ISSUE(2, 2);

    for (int kt = 0; kt < Kt; kt++) {
        const int s = kt % 3;
        CP_WAIT2();
        __syncthreads();

#pragma unroll
        for (int ks = 0; ks < 2; ks++) {
            uint4 a[4];
            uint2 b[4];
#pragma unroll
            for (int mt = 0; mt < 4; mt++)
                a[mt] = *(const uint4*)&As[s][(((warp_m * 4 + mt) * 2 + ks) * 32 + lane) * 4];
#pragma unroll
            for (int nt = 0; nt < 4; nt++)
                b[nt] = *(const uint2*)&Bs[s][(((warp_n * 4 + nt) * 2 + ks) * 32 + lane) * 2];
#pragma unroll
            for (int mt = 0; mt < 4; mt++)
#pragma unroll
                for (int nt = 0; nt < 4; nt++) {
                    uint32_t ar[4] = {a[mt].x, a[mt].y, a[mt].z, a[mt].w};
                    uint32_t br[2] = {b[nt].x, b[nt].y};
                    mma_tf32(c[mt][nt], ar, br);
                }
        }
        __syncthreads();
        GEMM_ISSUE(kt + 3, s);
    }
#undef GEMM_ISSUE

#pragma unroll
    for (int mt = 0; mt < 4; mt++) {
        int gr = by * 128 + warp_m * 64 + mt * 16 + (lane >> 2);
#pragma unroll
        for (int nt = 0; nt < 4; nt++) {
            int gc = bx * 128 + warp_n * 32 + nt * 8 + (lane & 3) * 2;
            float bx0 = bias[gc], bx1 = bias[gc + 1];
            float2 r0 = {c[mt][nt][0] + bx0, c[mt][nt][1] + bx1};
            float2 r1 = {c[mt][nt][2] + bx0, c[mt][nt][3] + bx1};
            *(float2*)(C + (size_t)gr * N + gc) = r0;
            *(float2*)(C + (size_t)(gr + 8) * N + gc) = r1;
        }
    }
}

// ---------------- fused per-head LayerNorm + RoPE ---------------------------
__global__ void ln_rope_kernel(float* __restrict__ buf,
                               const float* __restrict__ gamma,
                               const float* __restrict__ beta,
                               int heads, int seq)
{
    int row = blockIdx.x * blockDim.y + threadIdx.y;
    int total = seq * heads;
    if (row >= total) return;
    int s = row / heads;
    int lane = threadIdx.x;

    float* p = buf + (size_t)row * HEAD_DIM;
    float x0 = p[lane];
    float x1 = p[lane + 32];

    float sum = x0 + x1;
    float sq  = x0 * x0 + x1 * x1;
#pragma unroll
    for (int o = 16; o > 0; o >>= 1) {
        sum += __shfl_xor_sync(0xFFFFFFFFu, sum, o);
        sq  += __shfl_xor_sync(0xFFFFFFFFu, sq,  o);
    }
    float mean = sum * (1.0f / 64.0f);
    float var  = sq * (1.0f / 64.0f) - mean * mean;
    float inv  = rsqrtf(var + 1e-5f);

    float y0 = (x0 - mean) * inv * gamma[lane]      + beta[lane];
    float y1 = (x1 - mean) * inv * gamma[lane + 32] + beta[lane + 32];

    float freq = powf(10000.0f, -(float)lane * (1.0f / 32.0f));
    float ang  = (float)s * freq;
    float c, sn;
    sincosf(ang, &sn, &c);

    p[lane]      = y0 * c - y1 * sn;
    p[lane + 32] = y1 * c + y0 * sn;
}

// ============================================================================
// Tensor-core flash attention (tf32 mma, non-causal, GQA)
// Output written directly into A-fragment layout for the Wo GEMM.
// ============================================================================
#define AT_BK 32
#define KS_STRIDE 68
#define VS_STRIDE 72
#define PS_STRIDE 36

__global__ __launch_bounds__(128) void attn_mma_kernel(
    const float* __restrict__ q, const float* __restrict__ k,
    const float* __restrict__ v, uint32_t* __restrict__ o_frag)
{
    __shared__ uint32_t Ks[AT_BK * KS_STRIDE];
    __shared__ uint32_t Vs[AT_BK * VS_STRIDE];
    __shared__ __align__(8) uint32_t Ps[4][16 * PS_STRIDE];

    const int h   = blockIdx.y;
    const int g   = h >> 2;
    const int q0  = blockIdx.x * 64;
    const int tid = threadIdx.x;
    const int w   = tid >> 5;
    const int lane = tid & 31;
    const int gid  = lane >> 2;
    const int tig  = lane & 3;

    uint32_t qf[8][4];
    {
        const float* qp = q + (size_t)(q0 + w * 16) * HIDDEN + h * HEAD_DIM;
#pragma unroll
        for (int ks = 0; ks < 8; ks++) {
            qf[ks][0] = f2tf32(qp[(size_t)gid       * HIDDEN + ks * 8 + tig]);
            qf[ks][1] = f2tf32(qp[(size_t)(gid + 8) * HIDDEN + ks * 8 + tig]);
            qf[ks][2] = f2tf32(qp[(size_t)gid       * HIDDEN + ks * 8 + tig + 4]);
            qf[ks][3] = f2tf32(qp[(size_t)(gid + 8) * HIDDEN + ks * 8 + tig + 4]);
        }
    }

    float o[8][4];
#pragma unroll
    for (int nt = 0; nt < 8; nt++)
#pragma unroll
        for (int r = 0; r < 4; r++) o[nt][r] = 0.f;
    float m0 = -1e30f, m1 = -1e30f, l0 = 0.f, l1 = 0.f;

    const int f4i0 = tid;
    const float* kbase = k + g * HEAD_DIM;
    const float* vbase = v + g * HEAD_DIM;

    float4 kf[4], vf[4];
#pragma unroll
    for (int i = 0; i < 4; i++) {
        int f4 = f4i0 + i * 128;
        int row = f4 >> 4, c4 = (f4 & 15) * 4;
        kf[i] = *(const float4*)(kbase + (size_t)row * KV_DIM + c4);
        vf[i] = *(const float4*)(vbase + (size_t)row * KV_DIM + c4);
    }

    const int NT = SEQ / AT_BK;
    for (int t = 0; t < NT; t++) {
#pragma unroll
        for (int i = 0; i < 4; i++) {
            int f4 = f4i0 + i * 128;
            int row = f4 >> 4, c4 = (f4 & 15) * 4;
            uint32_t* kd = &Ks[row * KS_STRIDE + c4];
            kd[0] = f2tf32(kf[i].x); kd[1] = f2tf32(kf[i].y);
            kd[2] = f2tf32(kf[i].z); kd[3] = f2tf32(kf[i].w);
            uint32_t* vd = &Vs[row * VS_STRIDE + c4];
            vd[0] = f2tf32(vf[i].x); vd[1] = f2tf32(vf[i].y);
            vd[2] = f2tf32(vf[i].z); vd[3] = f2tf32(vf[i].w);
        }
        __syncthreads();

        if (t + 1 < NT) {
#pragma unroll
            for (int i = 0; i < 4; i++) {
                int f4 = f4i0 + i * 128;
                int row = f4 >> 4, c4 = (f4 & 15) * 4;
                size_t off = (size_t)((t + 1) * AT_BK + row) * KV_DIM + c4;
                kf[i] = *(const float4*)(kbase + off);
                vf[i] = *(const float4*)(vbase + off);
            }
        }

        float s[4][4];
#pragma unroll
        for (int nt = 0; nt < 4; nt++)
#pragma unroll
            for (int r = 0; r < 4; r++) s[nt][r] = 0.f;
#pragma unroll
        for (int ks = 0; ks < 8; ks++) {
#pragma unroll
            for (int nt = 0; nt < 4; nt++) {
                uint32_t b[2];
                const uint32_t* kp = &Ks[(nt * 8 + gid) * KS_STRIDE + ks * 8 + tig];
                b[0] = kp[0];
                b[1] = kp[4];
                mma_tf32(s[nt], qf[ks], b);
            }
        }

#pragma unroll
        for (int nt = 0; nt < 4; nt++)
#pragma unroll
            for (int r = 0; r < 4; r++) s[nt][r] *= 0.125f;

        float mr0 = s[0][0], mr1 = s[0][2];
#pragma unroll
        for (int nt = 0; nt < 4; nt++) {
            mr0 = fmaxf(mr0, fmaxf(s[nt][0], s[nt][1]));
            mr1 = fmaxf(mr1, fmaxf(s[nt][2], s[nt][3]));
        }
        mr0 = fmaxf(mr0, __shfl_xor_sync(0xFFFFFFFFu, mr0, 1));
        mr0 = fmaxf(mr0, __shfl_xor_sync(0xFFFFFFFFu, mr0, 2));
        mr1 = fmaxf(mr1, __shfl_xor_sync(0xFFFFFFFFu, mr1, 1));
        mr1 = fmaxf(mr1, __shfl_xor_sync(0xFFFFFFFFu, mr1, 2));

        float mn0 = fmaxf(m0, mr0), mn1 = fmaxf(m1, mr1);
        float a0 = __expf(m0 - mn0), a1 = __expf(m1 - mn1);
        m0 = mn0; m1 = mn1;

        float lp0 = 0.f, lp1 = 0.f;
        uint32_t* Pw = Ps[w];
#pragma unroll
        for (int nt = 0; nt < 4; nt++) {
            float p00 = __expf(s[nt][0] - mn0);
            float p01 = __expf(s[nt][1] - mn0);
            float p10 = __expf(s[nt][2] - mn1);
            float p11 = __expf(s[nt][3] - mn1);
            lp0 += p00 + p01;
            lp1 += p10 + p11;
            uint32_t* d0 = &Pw[gid * PS_STRIDE + nt * 8 + 2 * tig];
            d0[0] = f2tf32(p00); d0[1] = f2tf32(p01);
            uint32_t* d1 = &Pw[(gid + 8) * PS_STRIDE + nt * 8 + 2 * tig];
            d1[0] = f2tf32(p10); d1[1] = f2tf32(p11);
        }
        lp0 += __shfl_xor_sync(0xFFFFFFFFu, lp0, 1);
        lp0 += __shfl_xor_sync(0xFFFFFFFFu, lp0, 2);
        lp1 += __shfl_xor_sync(0xFFFFFFFFu, lp1, 1);
        lp1 += __shfl_xor_sync(0xFFFFFFFFu, lp1, 2);
        l0 = l0 * a0 + lp0;
        l1 = l1 * a1 + lp1;

#pragma unroll
        for (int nt = 0; nt < 8; nt++) {
            o[nt][0] *= a0; o[nt][1] *= a0;
            o[nt][2] *= a1; o[nt][3] *= a1;
        }
        __syncwarp();

#pragma unroll
        for (int kj = 0; kj < 4; kj++) {
            uint32_t a[4];
            a[0] = Pw[gid * PS_STRIDE + kj * 8 + tig];
            a[1] = Pw[(gid + 8) * PS_STRIDE + kj * 8 + tig];
            a[2] = Pw[gid * PS_STRIDE + kj * 8 + tig + 4];
            a[3] = Pw[(gid + 8) * PS_STRIDE + kj * 8 + tig + 4];
#pragma unroll
            for (int nt = 0; nt < 8; nt++) {
                uint32_t b[2];
                const uint32_t* vp = &Vs[(kj * 8 + tig) * VS_STRIDE + nt * 8 + gid];
                b[0] = vp[0];
                b[1] = vp[4 * VS_STRIDE];
                mma_tf32(o[nt], a, b);
            }
        }
        __syncthreads();
    }

    // ---- write O directly into A-fragment layout for the Wo GEMM ----
    // element (grow, gcol): by=grow>>7, mt=(grow&127)>>4, rr16=grow&15,
    // kt=gcol>>4, j=gcol&15, ks=j>>3, cc=j&7,
    // idx = ((by*Kt+kt)*2048) + ((mt*2+ks)*32 + (rr16&7)*4+(cc&3))*4 + (rr16>>3)+2*(cc>>2)
    const float il0 = 1.0f / l0, il1 = 1.0f / l1;
    const int Kt = HIDDEN / 16;                       // 128
    const int by = (q0 + w * 16) >> 7;
    const int mt_g = ((q0 & 127) >> 4) + w;           // 0..7
    uint32_t* dstb = o_frag + (size_t)by * Kt * 2048;
    const int cc0 = 2 * tig;
    const int rhi = cc0 >> 2;                         // tig>>1
    const int t0 = gid * 4 + (cc0 & 3);
    const int t1 = gid * 4 + ((cc0 + 1) & 3);
#pragma unroll
    for (int nt = 0; nt < 8; nt++) {
        int kt = h * 4 + (nt >> 1);
        int ks = nt & 1;
        uint32_t* base = dstb + (size_t)kt * 2048 + (size_t)((mt_g * 2 + ks) * 32) * 4;
        base[t0 * 4 + 2 * rhi]     = f2tf32(o[nt][0] * il0);
        base[t1 * 4 + 2 * rhi]     = f2tf32(o[nt][1] * il0);
        base[t0 * 4 + 1 + 2 * rhi] = f2tf32(o[nt][2] * il1);
        base[t1 * 4 + 1 + 2 * rhi] = f2tf32(o[nt][3] * il1);
    }
}

// ---------------- launch --------------------------------------------------
extern "C" void kernel_launch(void* const* d_in, const int* in_sizes, int n_in,
                              void* d_out, int out_size)
{
    const float* x   = (const float*)d_in[0];
    const float* Wq  = (const float*)d_in[1];
    const float* bq  = (const float*)d_in[2];
    const float* Wk  = (const float*)d_in[3];
    const float* bk  = (const float*)d_in[4];
    const float* Wv  = (const float*)d_in[5];
    const float* bv  = (const float*)d_in[6];
    const float* Wo  = (const float*)d_in[7];
    const float* bo  = (const float*)d_in[8];
    const float* q_g = (const float*)d_in[9];
    const float* q_b = (const float*)d_in[10];
    const float* k_g = (const float*)d_in[11];
    const float* k_b = (const float*)d_in[12];
    float* out = (float*)d_out;

    void *pq, *pk, *pv;
    void *pxa, *pwq, *pwk, *pwv, *pwo, *poa;
    cudaGetSymbolAddress(&pq, g_q);
    cudaGetSymbolAddress(&pk, g_k);
    cudaGetSymbolAddress(&pv, g_v);
    cudaGetSymbolAddress(&pxa, g_xa);
    cudaGetSymbolAddress(&pwq, g_wq);
    cudaGetSymbolAddress(&pwk, g_wk);
    cudaGetSymbolAddress(&pwv, g_wv);
    cudaGetSymbolAddress(&pwo, g_wo);
    cudaGetSymbolAddress(&poa, g_oa);
    float* fq = (float*)pq;
    float* fk = (float*)pk;
    float* fv = (float*)pv;
    uint32_t* xa = (uint32_t*)pxa;
    uint32_t* wqf = (uint32_t*)pwq;
    uint32_t* wkf = (uint32_t*)pwk;
    uint32_t* wvf = (uint32_t*)pwv;
    uint32_t* wof = (uint32_t*)pwo;
    uint32_t* oa = (uint32_t*)poa;

    // pre-shuffle operands into fragment layout
    {
        dim3 ga(HIDDEN / 16, SEQ / 128);          // (Kt, M/128)
        shuffle_a_kernel<<<ga, 256>>>(x, xa, SEQ, HIDDEN);
        dim3 gq(HIDDEN / 128, HIDDEN / 16);       // (NB, Kt)
        shuffle_b_kernel<<<gq, 256>>>(Wq, wqf, HIDDEN, HIDDEN);
        dim3 gk(KV_DIM / 128, HIDDEN / 16);
        shuffle_b_kernel<<<gk, 256>>>(Wk, wkf, HIDDEN, KV_DIM);
        shuffle_b_kernel<<<gk, 256>>>(Wv, wvf, HIDDEN, KV_DIM);
        shuffle_b_kernel<<<gq, 256>>>(Wo, wof, HIDDEN, HIDDEN);
    }

    // Q/K/V projections
    {
        dim3 grid(HIDDEN / 128, SEQ / 128);
        tf32_gemm_staged<<<grid, 256>>>(xa, wqf, bq, fq, SEQ, HIDDEN, HIDDEN);
    }
    {
        dim3 grid(KV_DIM / 128, SEQ / 128);
        tf32_gemm_staged<<<grid, 256>>>(xa, wkf, bk, fk, SEQ, KV_DIM, HIDDEN);
        tf32_gemm_staged<<<grid, 256>>>(xa, wvf, bv, fv, SEQ, KV_DIM, HIDDEN);
    }

    // per-head LN + RoPE
    {
        dim3 blk(32, 4);
        int rows_q = SEQ * N_HEADS;
        int rows_k = SEQ * N_KV;
        ln_rope_kernel<<<(rows_q + 3) / 4, blk>>>(fq, q_g, q_b, N_HEADS, SEQ);
        ln_rope_kernel<<<(rows_k + 3) / 4, blk>>>(fk, k_g, k_b, N_KV, SEQ);
    }

    // attention (writes fragment-staged O)
    {
        dim3 grid(SEQ / 64, N_HEADS);
        attn_mma_kernel<<<grid, 128>>>(fq, fk, fv, oa);
    }

    // output projection
    {
        dim3 grid(HIDDEN / 128, SEQ / 128);
        tf32_gemm_staged<<<grid, 256>>>(oa, wof, bo, out, SEQ, HIDDEN, HIDDEN);
    }
}

// round 6
// speedup vs baseline: 7.4292x; 1.0121x over previous
#include <cuda_runtime.h>
#include <cuda_bf16.h>
#include <math.h>
#include <stdint.h>

// ---------------- problem constants ----------------
#define SEQ      2048
#define HIDDEN   2048
#define N_HEADS  32
#define N_KV     8
#define HEAD_DIM 64
#define KV_DIM   (N_KV * HEAD_DIM)   // 512

// ---------------- scratch ----------------
__device__ float g_q[SEQ * HIDDEN];
__device__ float g_k[SEQ * KV_DIM];
__device__ float g_v[SEQ * KV_DIM];

// fragment-staged operands (tf32 bits). Tile = 2048 words (8KB).
// A layout: [M/128][K/16][2048] ; B layout: [K/16][N/128][2048]
__device__ uint32_t g_xa[(SEQ / 128) * (HIDDEN / 16) * 2048];
__device__ uint32_t g_wq[(HIDDEN / 16) * (HIDDEN / 128) * 2048];
__device__ uint32_t g_wk[(HIDDEN / 16) * (KV_DIM / 128) * 2048];
__device__ uint32_t g_wv[(HIDDEN / 16) * (KV_DIM / 128) * 2048];
__device__ uint32_t g_wo[(HIDDEN / 16) * (HIDDEN / 128) * 2048];
__device__ uint32_t g_oa[(SEQ / 128) * (HIDDEN / 16) * 2048];

__device__ __forceinline__ uint32_t f2tf32(float x) {
    uint32_t r;
    asm("cvt.rna.tf32.f32 %0, %1;" : "=r"(r) : "f"(x));
    return r;
}

__device__ __forceinline__ void mma_tf32(float c[4], const uint32_t a[4], const uint32_t b[2]) {
    asm volatile(
        "mma.sync.aligned.m16n8k8.row.col.f32.tf32.tf32.f32 "
        "{%0,%1,%2,%3},{%4,%5,%6,%7},{%8,%9},{%0,%1,%2,%3};"
        : "+f"(c[0]), "+f"(c[1]), "+f"(c[2]), "+f"(c[3])
        : "r"(a[0]), "r"(a[1]), "r"(a[2]), "r"(a[3]), "r"(b[0]), "r"(b[1]));
}

__device__ __forceinline__ uint32_t smem_u32(const void* p) {
    return (uint32_t)__cvta_generic_to_shared(p);
}
__device__ __forceinline__ void cp_async16(void* smem, const void* gmem) {
    asm volatile("cp.async.cg.shared.global [%0], [%1], 16;"
                 :: "r"(smem_u32(smem)), "l"(gmem));
}
#define CP_COMMIT() asm volatile("cp.async.commit_group;")
#define CP_WAIT2()  asm volatile("cp.async.wait_group 2;")

// ---------------- fragment scatter maps ------------------------------------
__device__ __forceinline__ void stage_a(uint32_t* dst, float4 v, int lin) {
    const int arow = lin >> 2;
    const int cbase = (lin & 3) * 4;
    float vv[4] = {v.x, v.y, v.z, v.w};
#pragma unroll
    for (int u = 0; u < 4; u++) {
        int j  = cbase + u;
        int mt = arow >> 4, rr = arow & 15;
        int ks = j >> 3,    cc = j & 7;
        int t   = (rr & 7) * 4 + (cc & 3);
        int reg = (rr >> 3) + 2 * (cc >> 2);
        dst[((mt * 2 + ks) * 32 + t) * 4 + reg] = f2tf32(vv[u]);
    }
}
__device__ __forceinline__ void stage_b(uint32_t* dst, float4 v, int lin) {
    const int brow = lin >> 5;
    const int cbase = (lin & 31) * 4;
    float vv[4] = {v.x, v.y, v.z, v.w};
#pragma unroll
    for (int u = 0; u < 4; u++) {
        int j  = cbase + u;
        int nt = j >> 3, cc = j & 7;
        int ks = brow >> 3, kk = brow & 7;
        int t   = cc * 4 + (kk & 3);
        int reg = kk >> 2;
        dst[((nt * 2 + ks) * 32 + t) * 2 + reg] = f2tf32(vv[u]);
    }
}

// ---------------- pre-shuffle kernels (2 tiles per block, MLP=4) ------------
__global__ __launch_bounds__(256) void shuffle_a_kernel(
    const float* __restrict__ A, uint32_t* __restrict__ Af, int M, int K)
{
    __shared__ __align__(16) uint32_t buf[2][2048];
    const int kt0 = blockIdx.x * 2, by = blockIdx.y;
    const int Kt = K / 16;
    const int tid = threadIdx.x;
    const int row0 = tid >> 2, c40 = (tid & 3) * 4;
    const int lin1 = 256 + tid;
    const int row1 = lin1 >> 2, c41 = (lin1 & 3) * 4;
    const float* Ab = A + (size_t)(by * 128) * K;

    float4 v[2][2];
#pragma unroll
    for (int t = 0; t < 2; t++) {
        const float* base = Ab + (kt0 + t) * 16;
        v[t][0] = *(const float4*)(base + (size_t)row0 * K + c40);
        v[t][1] = *(const float4*)(base + (size_t)row1 * K + c41);
    }
#pragma unroll
    for (int t = 0; t < 2; t++) {
        stage_a(buf[t], v[t][0], tid);
        stage_a(buf[t], v[t][1], lin1);
    }
    __syncthreads();
#pragma unroll
    for (int t = 0; t < 2; t++) {
        uint32_t* dst = Af + ((size_t)by * Kt + kt0 + t) * 2048;
        *(uint4*)(dst + tid * 4)        = *(const uint4*)(buf[t] + tid * 4);
        *(uint4*)(dst + 1024 + tid * 4) = *(const uint4*)(buf[t] + 1024 + tid * 4);
    }
}

__global__ __launch_bounds__(256) void shuffle_b_kernel(
    const float* __restrict__ B, uint32_t* __restrict__ Bf, int K, int N)
{
    __shared__ __align__(16) uint32_t buf[2][2048];
    const int bx = blockIdx.x, kt0 = blockIdx.y * 2;
    const int NB = N / 128;
    const int tid = threadIdx.x;
    const int brow0 = tid >> 5, c40 = (tid & 31) * 4;
    const int lin1 = 256 + tid;
    const int brow1 = lin1 >> 5, c41 = (lin1 & 31) * 4;

    float4 v[2][2];
#pragma unroll
    for (int t = 0; t < 2; t++) {
        const float* Bb = B + (size_t)((kt0 + t) * 16) * N + bx * 128;
        v[t][0] = *(const float4*)(Bb + (size_t)brow0 * N + c40);
        v[t][1] = *(const float4*)(Bb + (size_t)brow1 * N + c41);
    }
#pragma unroll
    for (int t = 0; t < 2; t++) {
        stage_b(buf[t], v[t][0], tid);
        stage_b(buf[t], v[t][1], lin1);
    }
    __syncthreads();
#pragma unroll
    for (int t = 0; t < 2; t++) {
        uint32_t* dst = Bf + ((size_t)(kt0 + t) * NB + bx) * 2048;
        *(uint4*)(dst + tid * 4)        = *(const uint4*)(buf[t] + tid * 4);
        *(uint4*)(dst + 1024 + tid * 4) = *(const uint4*)(buf[t] + 1024 + tid * 4);
    }
}

// ---------------- GEMM core: 4-stage cp.async, 1 barrier/iter ---------------
// smem: As = smem[0..8192), Bs = smem[8192..16384) words (64KB total).
__device__ __forceinline__ void gemm_core(
    const uint32_t* __restrict__ Abase,   // + kt*2048
    const uint32_t* __restrict__ Bf,      // + (kt*NB + bxl)*2048
    int Kt, int NB, int bxl,
    const float* __restrict__ bias, float* __restrict__ C, int N,
    int by, uint32_t* As, uint32_t* Bs)
{
    const int tid  = threadIdx.x;
    const int lane = tid & 31;
    const int wid  = tid >> 5;
    const int warp_m = wid >> 2;
    const int warp_n = wid & 3;

    float c[4][4][4];
#pragma unroll
    for (int i = 0; i < 4; i++)
#pragma unroll
        for (int j = 0; j < 4; j++)
#pragma unroll
            for (int r = 0; r < 4; r++) c[i][j][r] = 0.f;

    const int o0 = tid * 4;
    const int o1 = 1024 + tid * 4;

#define G_ISSUE(kt_, s_)                                                     \
    do {                                                                     \
        if ((kt_) < Kt) {                                                    \
            const uint32_t* ag = Abase + (size_t)(kt_) * 2048;               \
            const uint32_t* bg = Bf + ((size_t)(kt_) * NB + bxl) * 2048;     \
            cp_async16(&As[(s_) * 2048 + o0], ag + o0);                      \
            cp_async16(&As[(s_) * 2048 + o1], ag + o1);                      \
            cp_async16(&Bs[(s_) * 2048 + o0], bg + o0);                      \
            cp_async16(&Bs[(s_) * 2048 + o1], bg + o1);                      \
        }                                                                    \
        CP_COMMIT();                                                         \
    } while (0)

    G_ISSUE(0, 0);
    G_ISSUE(1, 1);
    G_ISSUE(2, 2);

    for (int kt = 0; kt < Kt; kt++) {
        const int s = kt & 3;
        CP_WAIT2();
        __syncthreads();
        // all warps finished compute of kt-1 -> safe to refill slot (kt+3)&3
        G_ISSUE(kt + 3, (kt + 3) & 3);

        const uint32_t* Ass = &As[s * 2048];
        const uint32_t* Bss = &Bs[s * 2048];
#pragma unroll
        for (int ks = 0; ks < 2; ks++) {
            uint4 a[4];
            uint2 b[4];
#pragma unroll
            for (int mt = 0; mt < 4; mt++)
                a[mt] = *(const uint4*)&Ass[(((warp_m * 4 + mt) * 2 + ks) * 32 + lane) * 4];
#pragma unroll
            for (int nt = 0; nt < 4; nt++)
                b[nt] = *(const uint2*)&Bss[(((warp_n * 4 + nt) * 2 + ks) * 32 + lane) * 2];
#pragma unroll
            for (int mt = 0; mt < 4; mt++)
#pragma unroll
                for (int nt = 0; nt < 4; nt++) {
                    uint32_t ar[4] = {a[mt].x, a[mt].y, a[mt].z, a[mt].w};
                    uint32_t br[2] = {b[nt].x, b[nt].y};
                    mma_tf32(c[mt][nt], ar, br);
                }
        }
    }
#undef G_ISSUE

#pragma unroll
    for (int mt = 0; mt < 4; mt++) {
        int gr = by * 128 + warp_m * 64 + mt * 16 + (lane >> 2);
#pragma unroll
        for (int nt = 0; nt < 4; nt++) {
            int gc = bxl * 128 + warp_n * 32 + nt * 8 + (lane & 3) * 2;
            float b0 = bias[gc], b1 = bias[gc + 1];
            float2 r0 = {c[mt][nt][0] + b0, c[mt][nt][1] + b1};
            float2 r1 = {c[mt][nt][2] + b0, c[mt][nt][3] + b1};
            *(float2*)(C + (size_t)gr * N + gc) = r0;
            *(float2*)(C + (size_t)(gr + 8) * N + gc) = r1;
        }
    }
}

// fused Q/K/V projection: grid (24, 16); x-tiles 0-15 -> Q, 16-19 -> K, 20-23 -> V
__global__ __launch_bounds__(256) void tf32_gemm_qkv(
    const uint32_t* __restrict__ Af,
    const uint32_t* __restrict__ Bq, const uint32_t* __restrict__ Bk,
    const uint32_t* __restrict__ Bv,
    const float* __restrict__ bq, const float* __restrict__ bk,
    const float* __restrict__ bv,
    float* __restrict__ cq, float* __restrict__ ck, float* __restrict__ cv)
{
    extern __shared__ __align__(16) uint32_t smem[];
    uint32_t* As = smem;
    uint32_t* Bs = smem + 4 * 2048;

    const int bx = blockIdx.x;
    const int by = blockIdx.y;
    const int Kt = HIDDEN / 16;

    const uint32_t* Bf;
    const float* bias;
    float* C;
    int N, NB, bxl;
    if (bx < 16)      { Bf = Bq; bias = bq; C = cq; N = HIDDEN; NB = 16; bxl = bx; }
    else if (bx < 20) { Bf = Bk; bias = bk; C = ck; N = KV_DIM; NB = 4;  bxl = bx - 16; }
    else              { Bf = Bv; bias = bv; C = cv; N = KV_DIM; NB = 4;  bxl = bx - 20; }

    gemm_core(Af + (size_t)by * Kt * 2048, Bf, Kt, NB, bxl, bias, C, N, by, As, Bs);
}

// generic staged GEMM (used for the O projection): grid (N/128, M/128)
__global__ __launch_bounds__(256) void tf32_gemm_staged(
    const uint32_t* __restrict__ Af, const uint32_t* __restrict__ Bf,
    const float* __restrict__ bias, float* __restrict__ C,
    int M, int N, int K)
{
    extern __shared__ __align__(16) uint32_t smem[];
    uint32_t* As = smem;
    uint32_t* Bs = smem + 4 * 2048;
    const int Kt = K / 16;
    gemm_core(Af + (size_t)blockIdx.y * Kt * 2048, Bf, Kt, N / 128, blockIdx.x,
              bias, C, N, blockIdx.y, As, Bs);
}

// ---------------- fused per-head LayerNorm + RoPE ---------------------------
__global__ void ln_rope_kernel(float* __restrict__ buf,
                               const float* __restrict__ gamma,
                               const float* __restrict__ beta,
                               int heads, int seq)
{
    int row = blockIdx.x * blockDim.y + threadIdx.y;
    int total = seq * heads;
    if (row >= total) return;
    int s = row / heads;
    int lane = threadIdx.x;

    float* p = buf + (size_t)row * HEAD_DIM;
    float x0 = p[lane];
    float x1 = p[lane + 32];

    float sum = x0 + x1;
    float sq  = x0 * x0 + x1 * x1;
#pragma unroll
    for (int o = 16; o > 0; o >>= 1) {
        sum += __shfl_xor_sync(0xFFFFFFFFu, sum, o);
        sq  += __shfl_xor_sync(0xFFFFFFFFu, sq,  o);
    }
    float mean = sum * (1.0f / 64.0f);
    float var  = sq * (1.0f / 64.0f) - mean * mean;
    float inv  = rsqrtf(var + 1e-5f);

    float y0 = (x0 - mean) * inv * gamma[lane]      + beta[lane];
    float y1 = (x1 - mean) * inv * gamma[lane + 32] + beta[lane + 32];

    float freq = powf(10000.0f, -(float)lane * (1.0f / 32.0f));
    float ang  = (float)s * freq;
    float c, sn;
    sincosf(ang, &sn, &c);

    p[lane]      = y0 * c - y1 * sn;
    p[lane + 32] = y1 * c + y0 * sn;
}

// ============================================================================
// Tensor-core flash attention (tf32 mma, non-causal, GQA)
// ============================================================================
#define AT_BK 32
#define KS_STRIDE 68
#define VS_STRIDE 72
#define PS_STRIDE 36

__global__ __launch_bounds__(128) void attn_mma_kernel(
    const float* __restrict__ q, const float* __restrict__ k,
    const float* __restrict__ v, uint32_t* __restrict__ o_frag)
{
    __shared__ uint32_t Ks[AT_BK * KS_STRIDE];
    __shared__ uint32_t Vs[AT_BK * VS_STRIDE];
    __shared__ __align__(8) uint32_t Ps[4][16 * PS_STRIDE];

    const int h   = blockIdx.y;
    const int g   = h >> 2;
    const int q0  = blockIdx.x * 64;
    const int tid = threadIdx.x;
    const int w   = tid >> 5;
    const int lane = tid & 31;
    const int gid  = lane >> 2;
    const int tig  = lane & 3;

    uint32_t qf[8][4];
    {
        const float* qp = q + (size_t)(q0 + w * 16) * HIDDEN + h * HEAD_DIM;
#pragma unroll
        for (int ks = 0; ks < 8; ks++) {
            qf[ks][0] = f2tf32(qp[(size_t)gid       * HIDDEN + ks * 8 + tig]);
            qf[ks][1] = f2tf32(qp[(size_t)(gid + 8) * HIDDEN + ks * 8 + tig]);
            qf[ks][2] = f2tf32(qp[(size_t)gid       * HIDDEN + ks * 8 + tig + 4]);
            qf[ks][3] = f2tf32(qp[(size_t)(gid + 8) * HIDDEN + ks * 8 + tig + 4]);
        }
    }

    float o[8][4];
#pragma unroll
    for (int nt = 0; nt < 8; nt++)
#pragma unroll
        for (int r = 0; r < 4; r++) o[nt][r] = 0.f;
    float m0 = -1e30f, m1 = -1e30f, l0 = 0.f, l1 = 0.f;

    const int f4i0 = tid;
    const float* kbase = k + g * HEAD_DIM;
    const float* vbase = v + g * HEAD_DIM;

    float4 kf[4], vf[4];
#pragma unroll
    for (int i = 0; i < 4; i++) {
        int f4 = f4i0 + i * 128;
        int row = f4 >> 4, c4 = (f4 & 15) * 4;
        kf[i] = *(const float4*)(kbase + (size_t)row * KV_DIM + c4);
        vf[i] = *(const float4*)(vbase + (size_t)row * KV_DIM + c4);
    }

    const int NT = SEQ / AT_BK;
    for (int t = 0; t < NT; t++) {
#pragma unroll
        for (int i = 0; i < 4; i++) {
            int f4 = f4i0 + i * 128;
            int row = f4 >> 4, c4 = (f4 & 15) * 4;
            uint32_t* kd = &Ks[row * KS_STRIDE + c4];
            kd[0] = f2tf32(kf[i].x); kd[1] = f2tf32(kf[i].y);
            kd[2] = f2tf32(kf[i].z); kd[3] = f2tf32(kf[i].w);
            uint32_t* vd = &Vs[row * VS_STRIDE + c4];
            vd[0] = f2tf32(vf[i].x); vd[1] = f2tf32(vf[i].y);
            vd[2] = f2tf32(vf[i].z); vd[3] = f2tf32(vf[i].w);
        }
        __syncthreads();

        if (t + 1 < NT) {
#pragma unroll
            for (int i = 0; i < 4; i++) {
                int f4 = f4i0 + i * 128;
                int row = f4 >> 4, c4 = (f4 & 15) * 4;
                size_t off = (size_t)((t + 1) * AT_BK + row) * KV_DIM + c4;
                kf[i] = *(const float4*)(kbase + off);
                vf[i] = *(const float4*)(vbase + off);
            }
        }

        float s[4][4];
#pragma unroll
        for (int nt = 0; nt < 4; nt++)
#pragma unroll
            for (int r = 0; r < 4; r++) s[nt][r] = 0.f;
#pragma unroll
        for (int ks = 0; ks < 8; ks++) {
#pragma unroll
            for (int nt = 0; nt < 4; nt++) {
                uint32_t b[2];
                const uint32_t* kp = &Ks[(nt * 8 + gid) * KS_STRIDE + ks * 8 + tig];
                b[0] = kp[0];
                b[1] = kp[4];
                mma_tf32(s[nt], qf[ks], b);
            }
        }

#pragma unroll
        for (int nt = 0; nt < 4; nt++)
#pragma unroll
            for (int r = 0; r < 4; r++) s[nt][r] *= 0.125f;

        float mr0 = s[0][0], mr1 = s[0][2];
#pragma unroll
        for (int nt = 0; nt < 4; nt++) {
            mr0 = fmaxf(mr0, fmaxf(s[nt][0], s[nt][1]));
            mr1 = fmaxf(mr1, fmaxf(s[nt][2], s[nt][3]));
        }
        mr0 = fmaxf(mr0, __shfl_xor_sync(0xFFFFFFFFu, mr0, 1));
        mr0 = fmaxf(mr0, __shfl_xor_sync(0xFFFFFFFFu, mr0, 2));
        mr1 = fmaxf(mr1, __shfl_xor_sync(0xFFFFFFFFu, mr1, 1));
        mr1 = fmaxf(mr1, __shfl_xor_sync(0xFFFFFFFFu, mr1, 2));

        float mn0 = fmaxf(m0, mr0), mn1 = fmaxf(m1, mr1);
        float a0 = __expf(m0 - mn0), a1 = __expf(m1 - mn1);
        m0 = mn0; m1 = mn1;

        float lp0 = 0.f, lp1 = 0.f;
        uint32_t* Pw = Ps[w];
#pragma unroll
        for (int nt = 0; nt < 4; nt++) {
            float p00 = __expf(s[nt][0] - mn0);
            float p01 = __expf(s[nt][1] - mn0);
            float p10 = __expf(s[nt][2] - mn1);
            float p11 = __expf(s[nt][3] - mn1);
            lp0 += p00 + p01;
            lp1 += p10 + p11;
            uint32_t* d0 = &Pw[gid * PS_STRIDE + nt * 8 + 2 * tig];
            d0[0] = f2tf32(p00); d0[1] = f2tf32(p01);
            uint32_t* d1 = &Pw[(gid + 8) * PS_STRIDE + nt * 8 + 2 * tig];
            d1[0] = f2tf32(p10); d1[1] = f2tf32(p11);
        }
        lp0 += __shfl_xor_sync(0xFFFFFFFFu, lp0, 1);
        lp0 += __shfl_xor_sync(0xFFFFFFFFu, lp0, 2);
        lp1 += __shfl_xor_sync(0xFFFFFFFFu, lp1, 1);
        lp1 += __shfl_xor_sync(0xFFFFFFFFu, lp1, 2);
        l0 = l0 * a0 + lp0;
        l1 = l1 * a1 + lp1;

#pragma unroll
        for (int nt = 0; nt < 8; nt++) {
            o[nt][0] *= a0; o[nt][1] *= a0;
            o[nt][2] *= a1; o[nt][3] *= a1;
        }
        __syncwarp();

#pragma unroll
        for (int kj = 0; kj < 4; kj++) {
            uint32_t a[4];
            a[0] = Pw[gid * PS_STRIDE + kj * 8 + tig];
            a[1] = Pw[(gid + 8) * PS_STRIDE + kj * 8 + tig];
            a[2] = Pw[gid * PS_STRIDE + kj * 8 + tig + 4];
            a[3] = Pw[(gid + 8) * PS_STRIDE + kj * 8 + tig + 4];
#pragma unroll
            for (int nt = 0; nt < 8; nt++) {
                uint32_t b[2];
                const uint32_t* vp = &Vs[(kj * 8 + tig) * VS_STRIDE + nt * 8 + gid];
                b[0] = vp[0];
                b[1] = vp[4 * VS_STRIDE];
                mma_tf32(o[nt], a, b);
            }
        }
        __syncthreads();
    }

    // write O directly into A-fragment layout for the Wo GEMM
    const float il0 = 1.0f / l0, il1 = 1.0f / l1;
    const int Kt = HIDDEN / 16;
    const int by = (q0 + w * 16) >> 7;
    const int mt_g = ((q0 & 127) >> 4) + w;
    uint32_t* dstb = o_frag + (size_t)by * Kt * 2048;
    const int cc0 = 2 * tig;
    const int rhi = cc0 >> 2;
    const int t0 = gid * 4 + (cc0 & 3);
    const int t1 = gid * 4 + ((cc0 + 1) & 3);
#pragma unroll
    for (int nt = 0; nt < 8; nt++) {
        int kt = h * 4 + (nt >> 1);
        int ks = nt & 1;
        uint32_t* base = dstb + (size_t)kt * 2048 + (size_t)((mt_g * 2 + ks) * 32) * 4;
        base[t0 * 4 + 2 * rhi]     = f2tf32(o[nt][0] * il0);
        base[t1 * 4 + 2 * rhi]     = f2tf32(o[nt][1] * il0);
        base[t0 * 4 + 1 + 2 * rhi] = f2tf32(o[nt][2] * il1);
        base[t1 * 4 + 1 + 2 * rhi] = f2tf32(o[nt][3] * il1);
    }
}

// ---------------- launch --------------------------------------------------
extern "C" void kernel_launch(void* const* d_in, const int* in_sizes, int n_in,
                              void* d_out, int out_size)
{
    const float* x   = (const float*)d_in[0];
    const float* Wq  = (const float*)d_in[1];
    const float* bq  = (const float*)d_in[2];
    const float* Wk  = (const float*)d_in[3];
    const float* bk  = (const float*)d_in[4];
    const float* Wv  = (const float*)d_in[5];
    const float* bv  = (const float*)d_in[6];
    const float* Wo  = (const float*)d_in[7];
    const float* bo  = (const float*)d_in[8];
    const float* q_g = (const float*)d_in[9];
    const float* q_b = (const float*)d_in[10];
    const float* k_g = (const float*)d_in[11];
    const float* k_b = (const float*)d_in[12];
    float* out = (float*)d_out;

    void *pq, *pk, *pv;
    void *pxa, *pwq, *pwk, *pwv, *pwo, *poa;
    cudaGetSymbolAddress(&pq, g_q);
    cudaGetSymbolAddress(&pk, g_k);
    cudaGetSymbolAddress(&pv, g_v);
    cudaGetSymbolAddress(&pxa, g_xa);
    cudaGetSymbolAddress(&pwq, g_wq);
    cudaGetSymbolAddress(&pwk, g_wk);
    cudaGetSymbolAddress(&pwv, g_wv);
    cudaGetSymbolAddress(&pwo, g_wo);
    cudaGetSymbolAddress(&poa, g_oa);
    float* fq = (float*)pq;
    float* fk = (float*)pk;
    float* fv = (float*)pv;
    uint32_t* xa = (uint32_t*)pxa;
    uint32_t* wqf = (uint32_t*)pwq;
    uint32_t* wkf = (uint32_t*)pwk;
    uint32_t* wvf = (uint32_t*)pwv;
    uint32_t* wof = (uint32_t*)pwo;
    uint32_t* oa = (uint32_t*)poa;

    const int GEMM_SMEM = 16 * 2048 * 4;   // 64 KB
    cudaFuncSetAttribute(tf32_gemm_qkv,
                         cudaFuncAttributeMaxDynamicSharedMemorySize, GEMM_SMEM);
    cudaFuncSetAttribute(tf32_gemm_staged,
                         cudaFuncAttributeMaxDynamicSharedMemorySize, GEMM_SMEM);

    // pre-shuffle operands into fragment layout
    {
        dim3 ga(HIDDEN / 32, SEQ / 128);          // (Kt/2, M/128)
        shuffle_a_kernel<<<ga, 256>>>(x, xa, SEQ, HIDDEN);
        dim3 gq(HIDDEN / 128, HIDDEN / 32);       // (NB, Kt/2)
        shuffle_b_kernel<<<gq, 256>>>(Wq, wqf, HIDDEN, HIDDEN);
        dim3 gk(KV_DIM / 128, HIDDEN / 32);
        shuffle_b_kernel<<<gk, 256>>>(Wk, wkf, HIDDEN, KV_DIM);
        shuffle_b_kernel<<<gk, 256>>>(Wv, wvf, HIDDEN, KV_DIM);
        shuffle_b_kernel<<<gq, 256>>>(Wo, wof, HIDDEN, HIDDEN);
    }

    // fused Q/K/V projections
    {
        dim3 grid(24, SEQ / 128);
        tf32_gemm_qkv<<<grid, 256, GEMM_SMEM>>>(xa, wqf, wkf, wvf,
                                                bq, bk, bv, fq, fk, fv);
    }

    // per-head LN + RoPE
    {
        dim3 blk(32, 4);
        int rows_q = SEQ * N_HEADS;
        int rows_k = SEQ * N_KV;
        ln_rope_kernel<<<(rows_q + 3) / 4, blk>>>(fq, q_g, q_b, N_HEADS, SEQ);
        ln_rope_kernel<<<(rows_k + 3) / 4, blk>>>(fk, k_g, k_b, N_KV, SEQ);
    }

    // attention (writes fragment-staged O)
    {
        dim3 grid(SEQ / 64, N_HEADS);
        attn_mma_kernel<<<grid, 128>>>(fq, fk, fv, oa);
    }

    // output projection
    {
        dim3 grid(HIDDEN / 128, SEQ / 128);
        tf32_gemm_staged<<<grid, 256, GEMM_SMEM>>>(oa, wof, bo, out, SEQ, HIDDEN, HIDDEN);
    }
}

// round 7
// speedup vs baseline: 7.7191x; 1.0390x over previous
#include <cuda_runtime.h>
#include <cuda_bf16.h>
#include <math.h>
#include <stdint.h>

// ---------------- problem constants ----------------
#define SEQ      2048
#define HIDDEN   2048
#define N_HEADS  32
#define N_KV     8
#define HEAD_DIM 64
#define KV_DIM   (N_KV * HEAD_DIM)   // 512

// ---------------- scratch ----------------
__device__ float g_q[SEQ * HIDDEN];
__device__ float g_k[SEQ * KV_DIM];
__device__ float g_v[SEQ * KV_DIM];

// fragment-staged operands (tf32 bits). Tile = 2048 words (8KB).
// A layout: [M/128][K/16][2048] ; B layout: [K/16][N/128][2048]
__device__ uint32_t g_xa[(SEQ / 128) * (HIDDEN / 16) * 2048];
__device__ uint32_t g_wq[(HIDDEN / 16) * (HIDDEN / 128) * 2048];
__device__ uint32_t g_wk[(HIDDEN / 16) * (KV_DIM / 128) * 2048];
__device__ uint32_t g_wv[(HIDDEN / 16) * (KV_DIM / 128) * 2048];
__device__ uint32_t g_wo[(HIDDEN / 16) * (HIDDEN / 128) * 2048];
__device__ uint32_t g_oa[(SEQ / 128) * (HIDDEN / 16) * 2048];

__device__ __forceinline__ uint32_t f2tf32(float x) {
    uint32_t r;
    asm("cvt.rna.tf32.f32 %0, %1;" : "=r"(r) : "f"(x));
    return r;
}

__device__ __forceinline__ void mma_tf32(float c[4], const uint32_t a[4], const uint32_t b[2]) {
    asm volatile(
        "mma.sync.aligned.m16n8k8.row.col.f32.tf32.tf32.f32 "
        "{%0,%1,%2,%3},{%4,%5,%6,%7},{%8,%9},{%0,%1,%2,%3};"
        : "+f"(c[0]), "+f"(c[1]), "+f"(c[2]), "+f"(c[3])
        : "r"(a[0]), "r"(a[1]), "r"(a[2]), "r"(a[3]), "r"(b[0]), "r"(b[1]));
}

__device__ __forceinline__ uint32_t smem_u32(const void* p) {
    return (uint32_t)__cvta_generic_to_shared(p);
}
__device__ __forceinline__ void cp_async16(void* smem, const void* gmem) {
    asm volatile("cp.async.cg.shared.global [%0], [%1], 16;"
                 :: "r"(smem_u32(smem)), "l"(gmem));
}
#define CP_COMMIT() asm volatile("cp.async.commit_group;")
#define CP_WAIT2()  asm volatile("cp.async.wait_group 2;")

// ---------------- fragment scatter maps ------------------------------------
__device__ __forceinline__ void stage_a(uint32_t* dst, float4 v, int lin) {
    const int arow = lin >> 2;
    const int cbase = (lin & 3) * 4;
    float vv[4] = {v.x, v.y, v.z, v.w};
#pragma unroll
    for (int u = 0; u < 4; u++) {
        int j  = cbase + u;
        int mt = arow >> 4, rr = arow & 15;
        int ks = j >> 3,    cc = j & 7;
        int t   = (rr & 7) * 4 + (cc & 3);
        int reg = (rr >> 3) + 2 * (cc >> 2);
        dst[((mt * 2 + ks) * 32 + t) * 4 + reg] = f2tf32(vv[u]);
    }
}
__device__ __forceinline__ void stage_b(uint32_t* dst, float4 v, int lin) {
    const int brow = lin >> 5;
    const int cbase = (lin & 31) * 4;
    float vv[4] = {v.x, v.y, v.z, v.w};
#pragma unroll
    for (int u = 0; u < 4; u++) {
        int j  = cbase + u;
        int nt = j >> 3, cc = j & 7;
        int ks = brow >> 3, kk = brow & 7;
        int t   = cc * 4 + (kk & 3);
        int reg = kk >> 2;
        dst[((nt * 2 + ks) * 32 + t) * 2 + reg] = f2tf32(vv[u]);
    }
}

// ---------------- combined shuffle (all operands, one launch) ---------------
__device__ __forceinline__ void shuffle_a_body(
    const float* __restrict__ A, uint32_t* __restrict__ Af,
    int K, int ktp, int by, uint32_t* buf)
{
    const int kt0 = ktp * 2;
    const int Kt = K / 16;
    const int tid = threadIdx.x;
    const int row0 = tid >> 2, c40 = (tid & 3) * 4;
    const int lin1 = 256 + tid;
    const int row1 = lin1 >> 2, c41 = (lin1 & 3) * 4;
    const float* Ab = A + (size_t)(by * 128) * K;

    float4 v[2][2];
#pragma unroll
    for (int t = 0; t < 2; t++) {
        const float* base = Ab + (kt0 + t) * 16;
        v[t][0] = *(const float4*)(base + (size_t)row0 * K + c40);
        v[t][1] = *(const float4*)(base + (size_t)row1 * K + c41);
    }
#pragma unroll
    for (int t = 0; t < 2; t++) {
        stage_a(buf + t * 2048, v[t][0], tid);
        stage_a(buf + t * 2048, v[t][1], lin1);
    }
    __syncthreads();
#pragma unroll
    for (int t = 0; t < 2; t++) {
        uint32_t* dst = Af + ((size_t)by * Kt + kt0 + t) * 2048;
        *(uint4*)(dst + tid * 4)        = *(const uint4*)(buf + t * 2048 + tid * 4);
        *(uint4*)(dst + 1024 + tid * 4) = *(const uint4*)(buf + t * 2048 + 1024 + tid * 4);
    }
}

__device__ __forceinline__ void shuffle_b_body(
    const float* __restrict__ B, uint32_t* __restrict__ Bf,
    int K, int N, int bx, int ktp, uint32_t* buf)
{
    const int kt0 = ktp * 2;
    const int NB = N / 128;
    const int tid = threadIdx.x;
    const int brow0 = tid >> 5, c40 = (tid & 31) * 4;
    const int lin1 = 256 + tid;
    const int brow1 = lin1 >> 5, c41 = (lin1 & 31) * 4;

    float4 v[2][2];
#pragma unroll
    for (int t = 0; t < 2; t++) {
        const float* Bb = B + (size_t)((kt0 + t) * 16) * N + bx * 128;
        v[t][0] = *(const float4*)(Bb + (size_t)brow0 * N + c40);
        v[t][1] = *(const float4*)(Bb + (size_t)brow1 * N + c41);
    }
#pragma unroll
    for (int t = 0; t < 2; t++) {
        stage_b(buf + t * 2048, v[t][0], tid);
        stage_b(buf + t * 2048, v[t][1], lin1);
    }
    __syncthreads();
#pragma unroll
    for (int t = 0; t < 2; t++) {
        uint32_t* dst = Bf + ((size_t)(kt0 + t) * NB + bx) * 2048;
        *(uint4*)(dst + tid * 4)        = *(const uint4*)(buf + t * 2048 + tid * 4);
        *(uint4*)(dst + 1024 + tid * 4) = *(const uint4*)(buf + t * 2048 + 1024 + tid * 4);
    }
}

// block ranges: [0,1024) xa | [1024,2048) wq | [2048,2304) wk |
//               [2304,2560) wv | [2560,3584) wo
__global__ __launch_bounds__(256) void shuffle_all_kernel(
    const float* __restrict__ x,
    const float* __restrict__ Wq, const float* __restrict__ Wk,
    const float* __restrict__ Wv, const float* __restrict__ Wo,
    uint32_t* __restrict__ xa, uint32_t* __restrict__ wq,
    uint32_t* __restrict__ wk, uint32_t* __restrict__ wv,
    uint32_t* __restrict__ wo)
{
    __shared__ __align__(16) uint32_t buf[2 * 2048];
    int b = blockIdx.x;
    if (b < 1024) {
        shuffle_a_body(x, xa, HIDDEN, b & 63, b >> 6, buf);
    } else if (b < 2048) {
        b -= 1024;
        shuffle_b_body(Wq, wq, HIDDEN, HIDDEN, b & 15, b >> 4, buf);
    } else if (b < 2304) {
        b -= 2048;
        shuffle_b_body(Wk, wk, HIDDEN, KV_DIM, b & 3, b >> 2, buf);
    } else if (b < 2560) {
        b -= 2304;
        shuffle_b_body(Wv, wv, HIDDEN, KV_DIM, b & 3, b >> 2, buf);
    } else {
        b -= 2560;
        shuffle_b_body(Wo, wo, HIDDEN, HIDDEN, b & 15, b >> 4, buf);
    }
}

// ---------------- GEMM core: 4-stage cp.async, 1 barrier/iter ---------------
__device__ __forceinline__ void gemm_core(
    const uint32_t* __restrict__ Abase,
    const uint32_t* __restrict__ Bf,
    int Kt, int NB, int bxl,
    const float* __restrict__ bias, float* __restrict__ C, int N,
    int by, uint32_t* As, uint32_t* Bs)
{
    const int tid  = threadIdx.x;
    const int lane = tid & 31;
    const int wid  = tid >> 5;
    const int warp_m = wid >> 2;
    const int warp_n = wid & 3;

    float c[4][4][4];
#pragma unroll
    for (int i = 0; i < 4; i++)
#pragma unroll
        for (int j = 0; j < 4; j++)
#pragma unroll
            for (int r = 0; r < 4; r++) c[i][j][r] = 0.f;

    const int o0 = tid * 4;
    const int o1 = 1024 + tid * 4;

#define G_ISSUE(kt_, s_)                                                     \
    do {                                                                     \
        if ((kt_) < Kt) {                                                    \
            const uint32_t* ag = Abase + (size_t)(kt_) * 2048;               \
            const uint32_t* bg = Bf + ((size_t)(kt_) * NB + bxl) * 2048;     \
            cp_async16(&As[(s_) * 2048 + o0], ag + o0);                      \
            cp_async16(&As[(s_) * 2048 + o1], ag + o1);                      \
            cp_async16(&Bs[(s_) * 2048 + o0], bg + o0);                      \
            cp_async16(&Bs[(s_) * 2048 + o1], bg + o1);                      \
        }                                                                    \
        CP_COMMIT();                                                         \
    } while (0)

    G_ISSUE(0, 0);
    G_ISSUE(1, 1);
    G_ISSUE(2, 2);

    for (int kt = 0; kt < Kt; kt++) {
        const int s = kt & 3;
        CP_WAIT2();
        __syncthreads();
        G_ISSUE(kt + 3, (kt + 3) & 3);

        const uint32_t* Ass = &As[s * 2048];
        const uint32_t* Bss = &Bs[s * 2048];
#pragma unroll
        for (int ks = 0; ks < 2; ks++) {
            uint4 a[4];
            uint2 b[4];
#pragma unroll
            for (int mt = 0; mt < 4; mt++)
                a[mt] = *(const uint4*)&Ass[(((warp_m * 4 + mt) * 2 + ks) * 32 + lane) * 4];
#pragma unroll
            for (int nt = 0; nt < 4; nt++)
                b[nt] = *(const uint2*)&Bss[(((warp_n * 4 + nt) * 2 + ks) * 32 + lane) * 2];
#pragma unroll
            for (int mt = 0; mt < 4; mt++)
#pragma unroll
                for (int nt = 0; nt < 4; nt++) {
                    uint32_t ar[4] = {a[mt].x, a[mt].y, a[mt].z, a[mt].w};
                    uint32_t br[2] = {b[nt].x, b[nt].y};
                    mma_tf32(c[mt][nt], ar, br);
                }
        }
    }
#undef G_ISSUE

#pragma unroll
    for (int mt = 0; mt < 4; mt++) {
        int gr = by * 128 + warp_m * 64 + mt * 16 + (lane >> 2);
#pragma unroll
        for (int nt = 0; nt < 4; nt++) {
            int gc = bxl * 128 + warp_n * 32 + nt * 8 + (lane & 3) * 2;
            float b0 = bias[gc], b1 = bias[gc + 1];
            float2 r0 = {c[mt][nt][0] + b0, c[mt][nt][1] + b1};
            float2 r1 = {c[mt][nt][2] + b0, c[mt][nt][3] + b1};
            *(float2*)(C + (size_t)gr * N + gc) = r0;
            *(float2*)(C + (size_t)(gr + 8) * N + gc) = r1;
        }
    }
}

__global__ __launch_bounds__(256) void tf32_gemm_qkv(
    const uint32_t* __restrict__ Af,
    const uint32_t* __restrict__ Bq, const uint32_t* __restrict__ Bk,
    const uint32_t* __restrict__ Bv,
    const float* __restrict__ bq, const float* __restrict__ bk,
    const float* __restrict__ bv,
    float* __restrict__ cq, float* __restrict__ ck, float* __restrict__ cv)
{
    extern __shared__ __align__(16) uint32_t smem[];
    uint32_t* As = smem;
    uint32_t* Bs = smem + 4 * 2048;

    const int bx = blockIdx.x;
    const int by = blockIdx.y;
    const int Kt = HIDDEN / 16;

    const uint32_t* Bf;
    const float* bias;
    float* C;
    int N, NB, bxl;
    if (bx < 16)      { Bf = Bq; bias = bq; C = cq; N = HIDDEN; NB = 16; bxl = bx; }
    else if (bx < 20) { Bf = Bk; bias = bk; C = ck; N = KV_DIM; NB = 4;  bxl = bx - 16; }
    else              { Bf = Bv; bias = bv; C = cv; N = KV_DIM; NB = 4;  bxl = bx - 20; }

    gemm_core(Af + (size_t)by * Kt * 2048, Bf, Kt, NB, bxl, bias, C, N, by, As, Bs);
}

__global__ __launch_bounds__(256) void tf32_gemm_staged(
    const uint32_t* __restrict__ Af, const uint32_t* __restrict__ Bf,
    const float* __restrict__ bias, float* __restrict__ C,
    int M, int N, int K)
{
    extern __shared__ __align__(16) uint32_t smem[];
    uint32_t* As = smem;
    uint32_t* Bs = smem + 4 * 2048;
    const int Kt = K / 16;
    gemm_core(Af + (size_t)blockIdx.y * Kt * 2048, Bf, Kt, N / 128, blockIdx.x,
              bias, C, N, blockIdx.y, As, Bs);
}

// ---------------- fused per-head LayerNorm + RoPE (q and k, one launch) -----
__global__ void ln_rope_all(float* __restrict__ qb_, float* __restrict__ kb_,
                            const float* __restrict__ q_g, const float* __restrict__ q_b,
                            const float* __restrict__ k_g, const float* __restrict__ k_b)
{
    int row = blockIdx.x * blockDim.y + threadIdx.y;
    const int QROWS = SEQ * N_HEADS;
    const int TOT = QROWS + SEQ * N_KV;
    if (row >= TOT) return;

    float* buf; const float* gamma; const float* beta; int heads; int lrow;
    if (row < QROWS) { buf = qb_; gamma = q_g; beta = q_b; heads = N_HEADS; lrow = row; }
    else             { buf = kb_; gamma = k_g; beta = k_b; heads = N_KV;   lrow = row - QROWS; }

    int s = lrow / heads;
    int lane = threadIdx.x;

    float* p = buf + (size_t)lrow * HEAD_DIM;
    float x0 = p[lane];
    float x1 = p[lane + 32];

    float sum = x0 + x1;
    float sq  = x0 * x0 + x1 * x1;
#pragma unroll
    for (int o = 16; o > 0; o >>= 1) {
        sum += __shfl_xor_sync(0xFFFFFFFFu, sum, o);
        sq  += __shfl_xor_sync(0xFFFFFFFFu, sq,  o);
    }
    float mean = sum * (1.0f / 64.0f);
    float var  = sq * (1.0f / 64.0f) - mean * mean;
    float inv  = rsqrtf(var + 1e-5f);

    float y0 = (x0 - mean) * inv * gamma[lane]      + beta[lane];
    float y1 = (x1 - mean) * inv * gamma[lane + 32] + beta[lane + 32];

    float freq = powf(10000.0f, -(float)lane * (1.0f / 32.0f));
    float ang  = (float)s * freq;
    float c, sn;
    sincosf(ang, &sn, &c);

    p[lane]      = y0 * c - y1 * sn;
    p[lane + 32] = y1 * c + y0 * sn;
}

// ============================================================================
// Tensor-core flash attention (tf32 mma, non-causal, GQA)
// BQ=128 q-rows per CTA, 8 warps (one m16 tile each); KV staged once per CTA.
// ============================================================================
#define AT_BK 32
#define KS_STRIDE 68
#define VS_STRIDE 72
#define PS_STRIDE 36

__global__ __launch_bounds__(256) void attn_mma_kernel(
    const float* __restrict__ q, const float* __restrict__ k,
    const float* __restrict__ v, uint32_t* __restrict__ o_frag)
{
    __shared__ uint32_t Ks[AT_BK * KS_STRIDE];
    __shared__ uint32_t Vs[AT_BK * VS_STRIDE];
    __shared__ __align__(8) uint32_t Ps[8][16 * PS_STRIDE];

    const int h   = blockIdx.y;
    const int g   = h >> 2;
    const int q0  = blockIdx.x * 128;
    const int tid = threadIdx.x;
    const int w   = tid >> 5;      // 0..7
    const int lane = tid & 31;
    const int gid  = lane >> 2;
    const int tig  = lane & 3;

    uint32_t qf[8][4];
    {
        const float* qp = q + (size_t)(q0 + w * 16) * HIDDEN + h * HEAD_DIM;
#pragma unroll
        for (int ks = 0; ks < 8; ks++) {
            qf[ks][0] = f2tf32(qp[(size_t)gid       * HIDDEN + ks * 8 + tig]);
            qf[ks][1] = f2tf32(qp[(size_t)(gid + 8) * HIDDEN + ks * 8 + tig]);
            qf[ks][2] = f2tf32(qp[(size_t)gid       * HIDDEN + ks * 8 + tig + 4]);
            qf[ks][3] = f2tf32(qp[(size_t)(gid + 8) * HIDDEN + ks * 8 + tig + 4]);
        }
    }

    float o[8][4];
#pragma unroll
    for (int nt = 0; nt < 8; nt++)
#pragma unroll
        for (int r = 0; r < 4; r++) o[nt][r] = 0.f;
    float m0 = -1e30f, m1 = -1e30f, l0 = 0.f, l1 = 0.f;

    // K/V tile: 32 rows x 64 cols = 512 float4 each; 256 threads -> 2 per thread
    const float* kbase = k + g * HEAD_DIM;
    const float* vbase = v + g * HEAD_DIM;

    float4 kf[2], vf[2];
#pragma unroll
    for (int i = 0; i < 2; i++) {
        int f4 = tid + i * 256;
        int row = f4 >> 4, c4 = (f4 & 15) * 4;
        kf[i] = *(const float4*)(kbase + (size_t)row * KV_DIM + c4);
        vf[i] = *(const float4*)(vbase + (size_t)row * KV_DIM + c4);
    }

    const int NT = SEQ / AT_BK;
    for (int t = 0; t < NT; t++) {
#pragma unroll
        for (int i = 0; i < 2; i++) {
            int f4 = tid + i * 256;
            int row = f4 >> 4, c4 = (f4 & 15) * 4;
            uint32_t* kd = &Ks[row * KS_STRIDE + c4];
            kd[0] = f2tf32(kf[i].x); kd[1] = f2tf32(kf[i].y);
            kd[2] = f2tf32(kf[i].z); kd[3] = f2tf32(kf[i].w);
            uint32_t* vd = &Vs[row * VS_STRIDE + c4];
            vd[0] = f2tf32(vf[i].x); vd[1] = f2tf32(vf[i].y);
            vd[2] = f2tf32(vf[i].z); vd[3] = f2tf32(vf[i].w);
        }
        __syncthreads();

        if (t + 1 < NT) {
#pragma unroll
            for (int i = 0; i < 2; i++) {
                int f4 = tid + i * 256;
                int row = f4 >> 4, c4 = (f4 & 15) * 4;
                size_t off = (size_t)((t + 1) * AT_BK + row) * KV_DIM + c4;
                kf[i] = *(const float4*)(kbase + off);
                vf[i] = *(const float4*)(vbase + off);
            }
        }

        float s[4][4];
#pragma unroll
        for (int nt = 0; nt < 4; nt++)
#pragma unroll
            for (int r = 0; r < 4; r++) s[nt][r] = 0.f;
#pragma unroll
        for (int ks = 0; ks < 8; ks++) {
#pragma unroll
            for (int nt = 0; nt < 4; nt++) {
                uint32_t b[2];
                const uint32_t* kp = &Ks[(nt * 8 + gid) * KS_STRIDE + ks * 8 + tig];
                b[0] = kp[0];
                b[1] = kp[4];
                mma_tf32(s[nt], qf[ks], b);
            }
        }

#pragma unroll
        for (int nt = 0; nt < 4; nt++)
#pragma unroll
            for (int r = 0; r < 4; r++) s[nt][r] *= 0.125f;

        float mr0 = s[0][0], mr1 = s[0][2];
#pragma unroll
        for (int nt = 0; nt < 4; nt++) {
            mr0 = fmaxf(mr0, fmaxf(s[nt][0], s[nt][1]));
            mr1 = fmaxf(mr1, fmaxf(s[nt][2], s[nt][3]));
        }
        mr0 = fmaxf(mr0, __shfl_xor_sync(0xFFFFFFFFu, mr0, 1));
        mr0 = fmaxf(mr0, __shfl_xor_sync(0xFFFFFFFFu, mr0, 2));
        mr1 = fmaxf(mr1, __shfl_xor_sync(0xFFFFFFFFu, mr1, 1));
        mr1 = fmaxf(mr1, __shfl_xor_sync(0xFFFFFFFFu, mr1, 2));

        float mn0 = fmaxf(m0, mr0), mn1 = fmaxf(m1, mr1);
        float a0 = __expf(m0 - mn0), a1 = __expf(m1 - mn1);
        m0 = mn0; m1 = mn1;

        float lp0 = 0.f, lp1 = 0.f;
        uint32_t* Pw = Ps[w];
#pragma unroll
        for (int nt = 0; nt < 4; nt++) {
            float p00 = __expf(s[nt][0] - mn0);
            float p01 = __expf(s[nt][1] - mn0);
            float p10 = __expf(s[nt][2] - mn1);
            float p11 = __expf(s[nt][3] - mn1);
            lp0 += p00 + p01;
            lp1 += p10 + p11;
            uint32_t* d0 = &Pw[gid * PS_STRIDE + nt * 8 + 2 * tig];
            d0[0] = f2tf32(p00); d0[1] = f2tf32(p01);
            uint32_t* d1 = &Pw[(gid + 8) * PS_STRIDE + nt * 8 + 2 * tig];
            d1[0] = f2tf32(p10); d1[1] = f2tf32(p11);
        }
        lp0 += __shfl_xor_sync(0xFFFFFFFFu, lp0, 1);
        lp0 += __shfl_xor_sync(0xFFFFFFFFu, lp0, 2);
        lp1 += __shfl_xor_sync(0xFFFFFFFFu, lp1, 1);
        lp1 += __shfl_xor_sync(0xFFFFFFFFu, lp1, 2);
        l0 = l0 * a0 + lp0;
        l1 = l1 * a1 + lp1;

#pragma unroll
        for (int nt = 0; nt < 8; nt++) {
            o[nt][0] *= a0; o[nt][1] *= a0;
            o[nt][2] *= a1; o[nt][3] *= a1;
        }
        __syncwarp();

#pragma unroll
        for (int kj = 0; kj < 4; kj++) {
            uint32_t a[4];
            a[0] = Pw[gid * PS_STRIDE + kj * 8 + tig];
            a[1] = Pw[(gid + 8) * PS_STRIDE + kj * 8 + tig];
            a[2] = Pw[gid * PS_STRIDE + kj * 8 + tig + 4];
            a[3] = Pw[(gid + 8) * PS_STRIDE + kj * 8 + tig + 4];
#pragma unroll
            for (int nt = 0; nt < 8; nt++) {
                uint32_t b[2];
                const uint32_t* vp = &Vs[(kj * 8 + tig) * VS_STRIDE + nt * 8 + gid];
                b[0] = vp[0];
                b[1] = vp[4 * VS_STRIDE];
                mma_tf32(o[nt], a, b);
            }
        }
        __syncthreads();
    }

    // write O directly into A-fragment layout for the Wo GEMM
    const float il0 = 1.0f / l0, il1 = 1.0f / l1;
    const int Kt = HIDDEN / 16;
    const int by = q0 >> 7;
    const int mt_g = w;
    uint32_t* dstb = o_frag + (size_t)by * Kt * 2048;
    const int cc0 = 2 * tig;
    const int rhi = cc0 >> 2;
    const int t0 = gid * 4 + (cc0 & 3);
    const int t1 = gid * 4 + ((cc0 + 1) & 3);
#pragma unroll
    for (int nt = 0; nt < 8; nt++) {
        int kt = h * 4 + (nt >> 1);
        int ks = nt & 1;
        uint32_t* base = dstb + (size_t)kt * 2048 + (size_t)((mt_g * 2 + ks) * 32) * 4;
        base[t0 * 4 + 2 * rhi]     = f2tf32(o[nt][0] * il0);
        base[t1 * 4 + 2 * rhi]     = f2tf32(o[nt][1] * il0);
        base[t0 * 4 + 1 + 2 * rhi] = f2tf32(o[nt][2] * il1);
        base[t1 * 4 + 1 + 2 * rhi] = f2tf32(o[nt][3] * il1);
    }
}

// ---------------- launch --------------------------------------------------
extern "C" void kernel_launch(void* const* d_in, const int* in_sizes, int n_in,
                              void* d_out, int out_size)
{
    const float* x   = (const float*)d_in[0];
    const float* Wq  = (const float*)d_in[1];
    const float* bq  = (const float*)d_in[2];
    const float* Wk  = (const float*)d_in[3];
    const float* bk  = (const float*)d_in[4];
    const float* Wv  = (const float*)d_in[5];
    const float* bv  = (const float*)d_in[6];
    const float* Wo  = (const float*)d_in[7];
    const float* bo  = (const float*)d_in[8];
    const float* q_g = (const float*)d_in[9];
    const float* q_b = (const float*)d_in[10];
    const float* k_g = (const float*)d_in[11];
    const float* k_b = (const float*)d_in[12];
    float* out = (float*)d_out;

    void *pq, *pk, *pv;
    void *pxa, *pwq, *pwk, *pwv, *pwo, *poa;
    cudaGetSymbolAddress(&pq, g_q);
    cudaGetSymbolAddress(&pk, g_k);
    cudaGetSymbolAddress(&pv, g_v);
    cudaGetSymbolAddress(&pxa, g_xa);
    cudaGetSymbolAddress(&pwq, g_wq);
    cudaGetSymbolAddress(&pwk, g_wk);
    cudaGetSymbolAddress(&pwv, g_wv);
    cudaGetSymbolAddress(&pwo, g_wo);
    cudaGetSymbolAddress(&poa, g_oa);
    float* fq = (float*)pq;
    float* fk = (float*)pk;
    float* fv = (float*)pv;
    uint32_t* xa = (uint32_t*)pxa;
    uint32_t* wqf = (uint32_t*)pwq;
    uint32_t* wkf = (uint32_t*)pwk;
    uint32_t* wvf = (uint32_t*)pwv;
    uint32_t* wof = (uint32_t*)pwo;
    uint32_t* oa = (uint32_t*)poa;

    const int GEMM_SMEM = 16 * 2048 * 4;   // 64 KB
    cudaFuncSetAttribute(tf32_gemm_qkv,
                         cudaFuncAttributeMaxDynamicSharedMemorySize, GEMM_SMEM);
    cudaFuncSetAttribute(tf32_gemm_staged,
                         cudaFuncAttributeMaxDynamicSharedMemorySize, GEMM_SMEM);

    // one combined shuffle launch (x + all 4 weights)
    shuffle_all_kernel<<<3584, 256>>>(x, Wq, Wk, Wv, Wo, xa, wqf, wkf, wvf, wof);

    // fused Q/K/V projections
    {
        dim3 grid(24, SEQ / 128);
        tf32_gemm_qkv<<<grid, 256, GEMM_SMEM>>>(xa, wqf, wkf, wvf,
                                                bq, bk, bv, fq, fk, fv);
    }

    // per-head LN + RoPE (q and k in one launch)
    {
        dim3 blk(32, 4);
        int rows = SEQ * N_HEADS + SEQ * N_KV;
        ln_rope_all<<<(rows + 3) / 4, blk>>>(fq, fk, q_g, q_b, k_g, k_b);
    }

    // attention (BQ=128, writes fragment-staged O)
    {
        dim3 grid(SEQ / 128, N_HEADS);
        attn_mma_kernel<<<grid, 256>>>(fq, fk, fv, oa);
    }

    // output projection
    {
        dim3 grid(HIDDEN / 128, SEQ / 128);
        tf32_gemm_staged<<<grid, 256, GEMM_SMEM>>>(oa, wof, bo, out, SEQ, HIDDEN, HIDDEN);
    }
}

// round 8
// speedup vs baseline: 7.9666x; 1.0321x over previous
#include <cuda_runtime.h>
#include <cuda_bf16.h>
#include <math.h>
#include <stdint.h>

// ---------------- problem constants ----------------
#define SEQ      2048
#define HIDDEN   2048
#define N_HEADS  32
#define N_KV     8
#define HEAD_DIM 64
#define KV_DIM   (N_KV * HEAD_DIM)   // 512

// ---------------- scratch ----------------
__device__ float g_q[SEQ * HIDDEN];
__device__ float g_k[SEQ * KV_DIM];
__device__ float g_v[SEQ * KV_DIM];

// fragment-staged operands (tf32 bits). Tile = 2048 words (8KB).
// A layout: [M/128][K/16][2048] ; B layout: [K/16][N/128][2048]
__device__ uint32_t g_xa[(SEQ / 128) * (HIDDEN / 16) * 2048];
__device__ uint32_t g_wq[(HIDDEN / 16) * (HIDDEN / 128) * 2048];
__device__ uint32_t g_wk[(HIDDEN / 16) * (KV_DIM / 128) * 2048];
__device__ uint32_t g_wv[(HIDDEN / 16) * (KV_DIM / 128) * 2048];
__device__ uint32_t g_wo[(HIDDEN / 16) * (HIDDEN / 128) * 2048];
__device__ uint32_t g_oa[(SEQ / 128) * (HIDDEN / 16) * 2048];

__device__ __forceinline__ uint32_t f2tf32(float x) {
    uint32_t r;
    asm("cvt.rna.tf32.f32 %0, %1;" : "=r"(r) : "f"(x));
    return r;
}

__device__ __forceinline__ void mma_tf32(float c[4], const uint32_t a[4], const uint32_t b[2]) {
    asm volatile(
        "mma.sync.aligned.m16n8k8.row.col.f32.tf32.tf32.f32 "
        "{%0,%1,%2,%3},{%4,%5,%6,%7},{%8,%9},{%0,%1,%2,%3};"
        : "+f"(c[0]), "+f"(c[1]), "+f"(c[2]), "+f"(c[3])
        : "r"(a[0]), "r"(a[1]), "r"(a[2]), "r"(a[3]), "r"(b[0]), "r"(b[1]));
}

__device__ __forceinline__ uint32_t smem_u32(const void* p) {
    return (uint32_t)__cvta_generic_to_shared(p);
}
__device__ __forceinline__ void cp_async16(void* smem, const void* gmem) {
    asm volatile("cp.async.cg.shared.global [%0], [%1], 16;"
                 :: "r"(smem_u32(smem)), "l"(gmem));
}
#define CP_COMMIT() asm volatile("cp.async.commit_group;")
#define CP_WAIT2()  asm volatile("cp.async.wait_group 2;")

// ---------------- fragment scatter maps ------------------------------------
__device__ __forceinline__ void stage_a(uint32_t* dst, float4 v, int lin) {
    const int arow = lin >> 2;
    const int cbase = (lin & 3) * 4;
    float vv[4] = {v.x, v.y, v.z, v.w};
#pragma unroll
    for (int u = 0; u < 4; u++) {
        int j  = cbase + u;
        int mt = arow >> 4, rr = arow & 15;
        int ks = j >> 3,    cc = j & 7;
        int t   = (rr & 7) * 4 + (cc & 3);
        int reg = (rr >> 3) + 2 * (cc >> 2);
        dst[((mt * 2 + ks) * 32 + t) * 4 + reg] = f2tf32(vv[u]);
    }
}
__device__ __forceinline__ void stage_b(uint32_t* dst, float4 v, int lin) {
    const int brow = lin >> 5;
    const int cbase = (lin & 31) * 4;
    float vv[4] = {v.x, v.y, v.z, v.w};
#pragma unroll
    for (int u = 0; u < 4; u++) {
        int j  = cbase + u;
        int nt = j >> 3, cc = j & 7;
        int ks = brow >> 3, kk = brow & 7;
        int t   = cc * 4 + (kk & 3);
        int reg = kk >> 2;
        dst[((nt * 2 + ks) * 32 + t) * 2 + reg] = f2tf32(vv[u]);
    }
}

// ---------------- combined shuffle (all operands, one launch) ---------------
__device__ __forceinline__ void shuffle_a_body(
    const float* __restrict__ A, uint32_t* __restrict__ Af,
    int K, int ktp, int by, uint32_t* buf)
{
    const int kt0 = ktp * 2;
    const int Kt = K / 16;
    const int tid = threadIdx.x;
    const int row0 = tid >> 2, c40 = (tid & 3) * 4;
    const int lin1 = 256 + tid;
    const int row1 = lin1 >> 2, c41 = (lin1 & 3) * 4;
    const float* Ab = A + (size_t)(by * 128) * K;

    float4 v[2][2];
#pragma unroll
    for (int t = 0; t < 2; t++) {
        const float* base = Ab + (kt0 + t) * 16;
        v[t][0] = *(const float4*)(base + (size_t)row0 * K + c40);
        v[t][1] = *(const float4*)(base + (size_t)row1 * K + c41);
    }
#pragma unroll
    for (int t = 0; t < 2; t++) {
        stage_a(buf + t * 2048, v[t][0], tid);
        stage_a(buf + t * 2048, v[t][1], lin1);
    }
    __syncthreads();
#pragma unroll
    for (int t = 0; t < 2; t++) {
        uint32_t* dst = Af + ((size_t)by * Kt + kt0 + t) * 2048;
        *(uint4*)(dst + tid * 4)        = *(const uint4*)(buf + t * 2048 + tid * 4);
        *(uint4*)(dst + 1024 + tid * 4) = *(const uint4*)(buf + t * 2048 + 1024 + tid * 4);
    }
}

__device__ __forceinline__ void shuffle_b_body(
    const float* __restrict__ B, uint32_t* __restrict__ Bf,
    int K, int N, int bx, int ktp, uint32_t* buf)
{
    const int kt0 = ktp * 2;
    const int NB = N / 128;
    const int tid = threadIdx.x;
    const int brow0 = tid >> 5, c40 = (tid & 31) * 4;
    const int lin1 = 256 + tid;
    const int brow1 = lin1 >> 5, c41 = (lin1 & 31) * 4;

    float4 v[2][2];
#pragma unroll
    for (int t = 0; t < 2; t++) {
        const float* Bb = B + (size_t)((kt0 + t) * 16) * N + bx * 128;
        v[t][0] = *(const float4*)(Bb + (size_t)brow0 * N + c40);
        v[t][1] = *(const float4*)(Bb + (size_t)brow1 * N + c41);
    }
#pragma unroll
    for (int t = 0; t < 2; t++) {
        stage_b(buf + t * 2048, v[t][0], tid);
        stage_b(buf + t * 2048, v[t][1], lin1);
    }
    __syncthreads();
#pragma unroll
    for (int t = 0; t < 2; t++) {
        uint32_t* dst = Bf + ((size_t)(kt0 + t) * NB + bx) * 2048;
        *(uint4*)(dst + tid * 4)        = *(const uint4*)(buf + t * 2048 + tid * 4);
        *(uint4*)(dst + 1024 + tid * 4) = *(const uint4*)(buf + t * 2048 + 1024 + tid * 4);
    }
}

__global__ __launch_bounds__(256) void shuffle_all_kernel(
    const float* __restrict__ x,
    const float* __restrict__ Wq, const float* __restrict__ Wk,
    const float* __restrict__ Wv, const float* __restrict__ Wo,
    uint32_t* __restrict__ xa, uint32_t* __restrict__ wq,
    uint32_t* __restrict__ wk, uint32_t* __restrict__ wv,
    uint32_t* __restrict__ wo)
{
    __shared__ __align__(16) uint32_t buf[2 * 2048];
    int b = blockIdx.x;
    if (b < 1024) {
        shuffle_a_body(x, xa, HIDDEN, b & 63, b >> 6, buf);
    } else if (b < 2048) {
        b -= 1024;
        shuffle_b_body(Wq, wq, HIDDEN, HIDDEN, b & 15, b >> 4, buf);
    } else if (b < 2304) {
        b -= 2048;
        shuffle_b_body(Wk, wk, HIDDEN, KV_DIM, b & 3, b >> 2, buf);
    } else if (b < 2560) {
        b -= 2304;
        shuffle_b_body(Wv, wv, HIDDEN, KV_DIM, b & 3, b >> 2, buf);
    } else {
        b -= 2560;
        shuffle_b_body(Wo, wo, HIDDEN, HIDDEN, b & 15, b >> 4, buf);
    }
}

// ---------------- GEMM core: 4-stage cp.async, 1 barrier/iter ---------------
__device__ __forceinline__ void gemm_core(
    const uint32_t* __restrict__ Abase,
    const uint32_t* __restrict__ Bf,
    int Kt, int NB, int bxl,
    const float* __restrict__ bias, float* __restrict__ C, int N,
    int by, uint32_t* As, uint32_t* Bs)
{
    const int tid  = threadIdx.x;
    const int lane = tid & 31;
    const int wid  = tid >> 5;
    const int warp_m = wid >> 2;
    const int warp_n = wid & 3;

    float c[4][4][4];
#pragma unroll
    for (int i = 0; i < 4; i++)
#pragma unroll
        for (int j = 0; j < 4; j++)
#pragma unroll
            for (int r = 0; r < 4; r++) c[i][j][r] = 0.f;

    const int o0 = tid * 4;
    const int o1 = 1024 + tid * 4;

#define G_ISSUE(kt_, s_)                                                     \
    do {                                                                     \
        if ((kt_) < Kt) {                                                    \
            const uint32_t* ag = Abase + (size_t)(kt_) * 2048;               \
            const uint32_t* bg = Bf + ((size_t)(kt_) * NB + bxl) * 2048;     \
            cp_async16(&As[(s_) * 2048 + o0], ag + o0);                      \
            cp_async16(&As[(s_) * 2048 + o1], ag + o1);                      \
            cp_async16(&Bs[(s_) * 2048 + o0], bg + o0);                      \
            cp_async16(&Bs[(s_) * 2048 + o1], bg + o1);                      \
        }                                                                    \
        CP_COMMIT();                                                         \
    } while (0)

    G_ISSUE(0, 0);
    G_ISSUE(1, 1);
    G_ISSUE(2, 2);

    for (int kt = 0; kt < Kt; kt++) {
        const int s = kt & 3;
        CP_WAIT2();
        __syncthreads();
        G_ISSUE(kt + 3, (kt + 3) & 3);

        const uint32_t* Ass = &As[s * 2048];
        const uint32_t* Bss = &Bs[s * 2048];
#pragma unroll
        for (int ks = 0; ks < 2; ks++) {
            uint4 a[4];
            uint2 b[4];
#pragma unroll
            for (int mt = 0; mt < 4; mt++)
                a[mt] = *(const uint4*)&Ass[(((warp_m * 4 + mt) * 2 + ks) * 32 + lane) * 4];
#pragma unroll
            for (int nt = 0; nt < 4; nt++)
                b[nt] = *(const uint2*)&Bss[(((warp_n * 4 + nt) * 2 + ks) * 32 + lane) * 2];
#pragma unroll
            for (int mt = 0; mt < 4; mt++)
#pragma unroll
                for (int nt = 0; nt < 4; nt++) {
                    uint32_t ar[4] = {a[mt].x, a[mt].y, a[mt].z, a[mt].w};
                    uint32_t br[2] = {b[nt].x, b[nt].y};
                    mma_tf32(c[mt][nt], ar, br);
                }
        }
    }
#undef G_ISSUE

#pragma unroll
    for (int mt = 0; mt < 4; mt++) {
        int gr = by * 128 + warp_m * 64 + mt * 16 + (lane >> 2);
#pragma unroll
        for (int nt = 0; nt < 4; nt++) {
            int gc = bxl * 128 + warp_n * 32 + nt * 8 + (lane & 3) * 2;
            float b0 = bias[gc], b1 = bias[gc + 1];
            float2 r0 = {c[mt][nt][0] + b0, c[mt][nt][1] + b1};
            float2 r1 = {c[mt][nt][2] + b0, c[mt][nt][3] + b1};
            *(float2*)(C + (size_t)gr * N + gc) = r0;
            *(float2*)(C + (size_t)(gr + 8) * N + gc) = r1;
        }
    }
}

__global__ __launch_bounds__(256) void tf32_gemm_qkv(
    const uint32_t* __restrict__ Af,
    const uint32_t* __restrict__ Bq, const uint32_t* __restrict__ Bk,
    const uint32_t* __restrict__ Bv,
    const float* __restrict__ bq, const float* __restrict__ bk,
    const float* __restrict__ bv,
    float* __restrict__ cq, float* __restrict__ ck, float* __restrict__ cv)
{
    extern __shared__ __align__(16) uint32_t smem[];
    uint32_t* As = smem;
    uint32_t* Bs = smem + 4 * 2048;

    const int bx = blockIdx.x;
    const int by = blockIdx.y;
    const int Kt = HIDDEN / 16;

    const uint32_t* Bf;
    const float* bias;
    float* C;
    int N, NB, bxl;
    if (bx < 16)      { Bf = Bq; bias = bq; C = cq; N = HIDDEN; NB = 16; bxl = bx; }
    else if (bx < 20) { Bf = Bk; bias = bk; C = ck; N = KV_DIM; NB = 4;  bxl = bx - 16; }
    else              { Bf = Bv; bias = bv; C = cv; N = KV_DIM; NB = 4;  bxl = bx - 20; }

    gemm_core(Af + (size_t)by * Kt * 2048, Bf, Kt, NB, bxl, bias, C, N, by, As, Bs);
}

__global__ __launch_bounds__(256) void tf32_gemm_staged(
    const uint32_t* __restrict__ Af, const uint32_t* __restrict__ Bf,
    const float* __restrict__ bias, float* __restrict__ C,
    int M, int N, int K)
{
    extern __shared__ __align__(16) uint32_t smem[];
    uint32_t* As = smem;
    uint32_t* Bs = smem + 4 * 2048;
    const int Kt = K / 16;
    gemm_core(Af + (size_t)blockIdx.y * Kt * 2048, Bf, Kt, N / 128, blockIdx.x,
              bias, C, N, blockIdx.y, As, Bs);
}

// ---------------- fused per-head LayerNorm + RoPE (q and k, one launch) -----
__global__ void ln_rope_all(float* __restrict__ qb_, float* __restrict__ kb_,
                            const float* __restrict__ q_g, const float* __restrict__ q_b,
                            const float* __restrict__ k_g, const float* __restrict__ k_b)
{
    int row = blockIdx.x * blockDim.y + threadIdx.y;
    const int QROWS = SEQ * N_HEADS;
    const int TOT = QROWS + SEQ * N_KV;
    if (row >= TOT) return;

    float* buf; const float* gamma; const float* beta; int heads; int lrow;
    if (row < QROWS) { buf = qb_; gamma = q_g; beta = q_b; heads = N_HEADS; lrow = row; }
    else             { buf = kb_; gamma = k_g; beta = k_b; heads = N_KV;   lrow = row - QROWS; }

    int s = lrow / heads;
    int lane = threadIdx.x;

    float* p = buf + (size_t)lrow * HEAD_DIM;
    float x0 = p[lane];
    float x1 = p[lane + 32];

    float sum = x0 + x1;
    float sq  = x0 * x0 + x1 * x1;
#pragma unroll
    for (int o = 16; o > 0; o >>= 1) {
        sum += __shfl_xor_sync(0xFFFFFFFFu, sum, o);
        sq  += __shfl_xor_sync(0xFFFFFFFFu, sq,  o);
    }
    float mean = sum * (1.0f / 64.0f);
    float var  = sq * (1.0f / 64.0f) - mean * mean;
    float inv  = rsqrtf(var + 1e-5f);

    float y0 = (x0 - mean) * inv * gamma[lane]      + beta[lane];
    float y1 = (x1 - mean) * inv * gamma[lane + 32] + beta[lane + 32];

    float freq = powf(10000.0f, -(float)lane * (1.0f / 32.0f));
    float ang  = (float)s * freq;
    float c, sn;
    sincosf(ang, &sn, &c);

    p[lane]      = y0 * c - y1 * sn;
    p[lane + 32] = y1 * c + y0 * sn;
}

// ============================================================================
// Tensor-core flash attention (tf32 mma, non-causal, GQA)
// BQ=128, 4 warps, each warp owns m32 (2 m16 tiles). K/V b-fragments are
// loaded once per (ks,nt) and reused across both m-tiles -> smem traffic
// per unit math halves vs m16-per-warp.
// ============================================================================
#define AT_BK 32
#define KS_STRIDE 68
#define VS_STRIDE 72
#define PS_STRIDE 36

__global__ __launch_bounds__(128) void attn_mma_kernel(
    const float* __restrict__ q, const float* __restrict__ k,
    const float* __restrict__ v, uint32_t* __restrict__ o_frag)
{
    __shared__ uint32_t Ks[AT_BK * KS_STRIDE];
    __shared__ uint32_t Vs[AT_BK * VS_STRIDE];
    __shared__ __align__(8) uint32_t Ps[4][2][16 * PS_STRIDE];

    const int h   = blockIdx.y;
    const int g   = h >> 2;
    const int q0  = blockIdx.x * 128;
    const int tid = threadIdx.x;
    const int w   = tid >> 5;      // 0..3
    const int lane = tid & 31;
    const int gid  = lane >> 2;
    const int tig  = lane & 3;

    // Q fragments: warp w owns rows q0 + w*32 .. +31 (2 m16 tiles)
    uint32_t qf[2][8][4];
#pragma unroll
    for (int mt = 0; mt < 2; mt++) {
        const float* qp = q + (size_t)(q0 + w * 32 + mt * 16) * HIDDEN + h * HEAD_DIM;
#pragma unroll
        for (int ks = 0; ks < 8; ks++) {
            qf[mt][ks][0] = f2tf32(qp[(size_t)gid       * HIDDEN + ks * 8 + tig]);
            qf[mt][ks][1] = f2tf32(qp[(size_t)(gid + 8) * HIDDEN + ks * 8 + tig]);
            qf[mt][ks][2] = f2tf32(qp[(size_t)gid       * HIDDEN + ks * 8 + tig + 4]);
            qf[mt][ks][3] = f2tf32(qp[(size_t)(gid + 8) * HIDDEN + ks * 8 + tig + 4]);
        }
    }

    float o[2][8][4];
#pragma unroll
    for (int mt = 0; mt < 2; mt++)
#pragma unroll
        for (int nt = 0; nt < 8; nt++)
#pragma unroll
            for (int r = 0; r < 4; r++) o[mt][nt][r] = 0.f;
    float m[2][2] = {{-1e30f, -1e30f}, {-1e30f, -1e30f}};
    float l[2][2] = {{0.f, 0.f}, {0.f, 0.f}};

    // K/V tile: 32 rows x 64 cols = 512 float4 each; 128 threads -> 4 per thread
    const float* kbase = k + g * HEAD_DIM;
    const float* vbase = v + g * HEAD_DIM;

    float4 kf[4], vf[4];
#pragma unroll
    for (int i = 0; i < 4; i++) {
        int f4 = tid + i * 128;
        int row = f4 >> 4, c4 = (f4 & 15) * 4;
        kf[i] = *(const float4*)(kbase + (size_t)row * KV_DIM + c4);
        vf[i] = *(const float4*)(vbase + (size_t)row * KV_DIM + c4);
    }

    const int NT = SEQ / AT_BK;
    for (int t = 0; t < NT; t++) {
        // stage current tile (tf32 bits)
#pragma unroll
        for (int i = 0; i < 4; i++) {
            int f4 = tid + i * 128;
            int row = f4 >> 4, c4 = (f4 & 15) * 4;
            uint32_t* kd = &Ks[row * KS_STRIDE + c4];
            kd[0] = f2tf32(kf[i].x); kd[1] = f2tf32(kf[i].y);
            kd[2] = f2tf32(kf[i].z); kd[3] = f2tf32(kf[i].w);
            uint32_t* vd = &Vs[row * VS_STRIDE + c4];
            vd[0] = f2tf32(vf[i].x); vd[1] = f2tf32(vf[i].y);
            vd[2] = f2tf32(vf[i].z); vd[3] = f2tf32(vf[i].w);
        }
        __syncthreads();

        // ---- scores for BOTH m-tiles; K b-fragment loaded once ----
        float s[2][4][4];
#pragma unroll
        for (int mt = 0; mt < 2; mt++)
#pragma unroll
            for (int nt = 0; nt < 4; nt++)
#pragma unroll
                for (int r = 0; r < 4; r++) s[mt][nt][r] = 0.f;
#pragma unroll
        for (int ks = 0; ks < 8; ks++) {
#pragma unroll
            for (int nt = 0; nt < 4; nt++) {
                uint32_t b[2];
                const uint32_t* kp = &Ks[(nt * 8 + gid) * KS_STRIDE + ks * 8 + tig];
                b[0] = kp[0];
                b[1] = kp[4];
                mma_tf32(s[0][nt], qf[0][ks], b);
                mma_tf32(s[1][nt], qf[1][ks], b);
            }
        }

        // prefetch next tile (latency hidden under softmax + PV)
        if (t + 1 < NT) {
#pragma unroll
            for (int i = 0; i < 4; i++) {
                int f4 = tid + i * 128;
                int row = f4 >> 4, c4 = (f4 & 15) * 4;
                size_t off = (size_t)((t + 1) * AT_BK + row) * KV_DIM + c4;
                kf[i] = *(const float4*)(kbase + off);
                vf[i] = *(const float4*)(vbase + off);
            }
        }

        // ---- online softmax per m-tile ----
#pragma unroll
        for (int mt = 0; mt < 2; mt++) {
#pragma unroll
            for (int nt = 0; nt < 4; nt++)
#pragma unroll
                for (int r = 0; r < 4; r++) s[mt][nt][r] *= 0.125f;

            float mr0 = s[mt][0][0], mr1 = s[mt][0][2];
#pragma unroll
            for (int nt = 0; nt < 4; nt++) {
                mr0 = fmaxf(mr0, fmaxf(s[mt][nt][0], s[mt][nt][1]));
                mr1 = fmaxf(mr1, fmaxf(s[mt][nt][2], s[mt][nt][3]));
            }
            mr0 = fmaxf(mr0, __shfl_xor_sync(0xFFFFFFFFu, mr0, 1));
            mr0 = fmaxf(mr0, __shfl_xor_sync(0xFFFFFFFFu, mr0, 2));
            mr1 = fmaxf(mr1, __shfl_xor_sync(0xFFFFFFFFu, mr1, 1));
            mr1 = fmaxf(mr1, __shfl_xor_sync(0xFFFFFFFFu, mr1, 2));

            float mn0 = fmaxf(m[mt][0], mr0), mn1 = fmaxf(m[mt][1], mr1);
            float a0 = __expf(m[mt][0] - mn0), a1 = __expf(m[mt][1] - mn1);
            m[mt][0] = mn0; m[mt][1] = mn1;

            float lp0 = 0.f, lp1 = 0.f;
            uint32_t* Pw = Ps[w][mt];
#pragma unroll
            for (int nt = 0; nt < 4; nt++) {
                float p00 = __expf(s[mt][nt][0] - mn0);
                float p01 = __expf(s[mt][nt][1] - mn0);
                float p10 = __expf(s[mt][nt][2] - mn1);
                float p11 = __expf(s[mt][nt][3] - mn1);
                lp0 += p00 + p01;
                lp1 += p10 + p11;
                uint32_t* d0 = &Pw[gid * PS_STRIDE + nt * 8 + 2 * tig];
                d0[0] = f2tf32(p00); d0[1] = f2tf32(p01);
                uint32_t* d1 = &Pw[(gid + 8) * PS_STRIDE + nt * 8 + 2 * tig];
                d1[0] = f2tf32(p10); d1[1] = f2tf32(p11);
            }
            lp0 += __shfl_xor_sync(0xFFFFFFFFu, lp0, 1);
            lp0 += __shfl_xor_sync(0xFFFFFFFFu, lp0, 2);
            lp1 += __shfl_xor_sync(0xFFFFFFFFu, lp1, 1);
            lp1 += __shfl_xor_sync(0xFFFFFFFFu, lp1, 2);
            l[mt][0] = l[mt][0] * a0 + lp0;
            l[mt][1] = l[mt][1] * a1 + lp1;

#pragma unroll
            for (int nt = 0; nt < 8; nt++) {
                o[mt][nt][0] *= a0; o[mt][nt][1] *= a0;
                o[mt][nt][2] *= a1; o[mt][nt][3] *= a1;
            }
        }
        __syncwarp();

        // ---- O += P @ V ; V b-fragment loaded once, used for both m-tiles --
#pragma unroll
        for (int kj = 0; kj < 4; kj++) {
            uint32_t a0[4], a1[4];
            uint32_t* P0 = Ps[w][0];
            uint32_t* P1 = Ps[w][1];
            a0[0] = P0[gid * PS_STRIDE + kj * 8 + tig];
            a0[1] = P0[(gid + 8) * PS_STRIDE + kj * 8 + tig];
            a0[2] = P0[gid * PS_STRIDE + kj * 8 + tig + 4];
            a0[3] = P0[(gid + 8) * PS_STRIDE + kj * 8 + tig + 4];
            a1[0] = P1[gid * PS_STRIDE + kj * 8 + tig];
            a1[1] = P1[(gid + 8) * PS_STRIDE + kj * 8 + tig];
            a1[2] = P1[gid * PS_STRIDE + kj * 8 + tig + 4];
            a1[3] = P1[(gid + 8) * PS_STRIDE + kj * 8 + tig + 4];
#pragma unroll
            for (int nt = 0; nt < 8; nt++) {
                uint32_t b[2];
                const uint32_t* vp = &Vs[(kj * 8 + tig) * VS_STRIDE + nt * 8 + gid];
                b[0] = vp[0];
                b[1] = vp[4 * VS_STRIDE];
                mma_tf32(o[0][nt], a0, b);
                mma_tf32(o[1][nt], a1, b);
            }
        }
        __syncthreads();
    }

    // ---- write O directly into A-fragment layout for the Wo GEMM ----
    const int Kt = HIDDEN / 16;
    const int by = q0 >> 7;
    uint32_t* dstb = o_frag + (size_t)by * Kt * 2048;
    const int cc0 = 2 * tig;
    const int rhi = cc0 >> 2;
    const int t0 = gid * 4 + (cc0 & 3);
    const int t1 = gid * 4 + ((cc0 + 1) & 3);
#pragma unroll
    for (int mt = 0; mt < 2; mt++) {
        const float il0 = 1.0f / l[mt][0], il1 = 1.0f / l[mt][1];
        const int mt_g = w * 2 + mt;
#pragma unroll
        for (int nt = 0; nt < 8; nt++) {
            int kt = h * 4 + (nt >> 1);
            int ks = nt & 1;
            uint32_t* base = dstb + (size_t)kt * 2048 + (size_t)((mt_g * 2 + ks) * 32) * 4;
            base[t0 * 4 + 2 * rhi]     = f2tf32(o[mt][nt][0] * il0);
            base[t1 * 4 + 2 * rhi]     = f2tf32(o[mt][nt][1] * il0);
            base[t0 * 4 + 1 + 2 * rhi] = f2tf32(o[mt][nt][2] * il1);
            base[t1 * 4 + 1 + 2 * rhi] = f2tf32(o[mt][nt][3] * il1);
        }
    }
}

// ---------------- launch --------------------------------------------------
extern "C" void kernel_launch(void* const* d_in, const int* in_sizes, int n_in,
                              void* d_out, int out_size)
{
    const float* x   = (const float*)d_in[0];
    const float* Wq  = (const float*)d_in[1];
    const float* bq  = (const float*)d_in[2];
    const float* Wk  = (const float*)d_in[3];
    const float* bk  = (const float*)d_in[4];
    const float* Wv  = (const float*)d_in[5];
    const float* bv  = (const float*)d_in[6];
    const float* Wo  = (const float*)d_in[7];
    const float* bo  = (const float*)d_in[8];
    const float* q_g = (const float*)d_in[9];
    const float* q_b = (const float*)d_in[10];
    const float* k_g = (const float*)d_in[11];
    const float* k_b = (const float*)d_in[12];
    float* out = (float*)d_out;

    void *pq, *pk, *pv;
    void *pxa, *pwq, *pwk, *pwv, *pwo, *poa;
    cudaGetSymbolAddress(&pq, g_q);
    cudaGetSymbolAddress(&pk, g_k);
    cudaGetSymbolAddress(&pv, g_v);
    cudaGetSymbolAddress(&pxa, g_xa);
    cudaGetSymbolAddress(&pwq, g_wq);
    cudaGetSymbolAddress(&pwk, g_wk);
    cudaGetSymbolAddress(&pwv, g_wv);
    cudaGetSymbolAddress(&pwo, g_wo);
    cudaGetSymbolAddress(&poa, g_oa);
    float* fq = (float*)pq;
    float* fk = (float*)pk;
    float* fv = (float*)pv;
    uint32_t* xa = (uint32_t*)pxa;
    uint32_t* wqf = (uint32_t*)pwq;
    uint32_t* wkf = (uint32_t*)pwk;
    uint32_t* wvf = (uint32_t*)pwv;
    uint32_t* wof = (uint32_t*)pwo;
    uint32_t* oa = (uint32_t*)poa;

    const int GEMM_SMEM = 16 * 2048 * 4;   // 64 KB
    cudaFuncSetAttribute(tf32_gemm_qkv,
                         cudaFuncAttributeMaxDynamicSharedMemorySize, GEMM_SMEM);
    cudaFuncSetAttribute(tf32_gemm_staged,
                         cudaFuncAttributeMaxDynamicSharedMemorySize, GEMM_SMEM);

    // one combined shuffle launch (x + all 4 weights)
    shuffle_all_kernel<<<3584, 256>>>(x, Wq, Wk, Wv, Wo, xa, wqf, wkf, wvf, wof);

    // fused Q/K/V projections
    {
        dim3 grid(24, SEQ / 128);
        tf32_gemm_qkv<<<grid, 256, GEMM_SMEM>>>(xa, wqf, wkf, wvf,
                                                bq, bk, bv, fq, fk, fv);
    }

    // per-head LN + RoPE (q and k in one launch)
    {
        dim3 blk(32, 4);
        int rows = SEQ * N_HEADS + SEQ * N_KV;
        ln_rope_all<<<(rows + 3) / 4, blk>>>(fq, fk, q_g, q_b, k_g, k_b);
    }

    // attention (BQ=128, 4 warps x m32)
    {
        dim3 grid(SEQ / 128, N_HEADS);
        attn_mma_kernel<<<grid, 128>>>(fq, fk, fv, oa);
    }

    // output projection
    {
        dim3 grid(HIDDEN / 128, SEQ / 128);
        tf32_gemm_staged<<<grid, 256, GEMM_SMEM>>>(oa, wof, bo, out, SEQ, HIDDEN, HIDDEN);
    }
}